// round 2
// baseline (speedup 1.0000x reference)
#include <cuda_runtime.h>
#include <cstdint>

#define NN   20000
#define EE   320000
#define DIN  2048
#define H1D  512
#define H2D  128
#define H3D  32
#define LN_EPS 1e-5f
#define ET   (EE + NN)   // edges incl. self loops

// ---------------- scratch (static device globals; no allocation) -------------
__device__ float g_xw1[NN * H1D];
__device__ float g_agg1[NN * H1D];
__device__ float g_h1[NN * H1D];
__device__ float g_xw2[NN * H2D];
__device__ float g_agg2[NN * H2D];
__device__ float g_h2[NN * H2D];
__device__ float g_xw3[NN * H3D];
__device__ float g_agg3[NN * H3D];
__device__ float g_h3[NN * H3D];
__device__ float g_xwg[NN * H3D];
__device__ float g_aggg[NN * H3D];
__device__ float g_deg[NN];
__device__ float g_dinv[NN];
__device__ float g_as[NN];
__device__ float g_ad[NN];
__device__ float g_amax[NN];
__device__ float g_denom[NN];
__device__ float g_earr[ET];
__device__ float g_enorm[ET];
__device__ int   g_src[ET];
__device__ int   g_dst[ET];
__device__ float g_pool[H3D];
__device__ int   g_is32;

// ---------------- init ------------------------------------------------------
__global__ void k_init() {
    int i = blockIdx.x * blockDim.x + threadIdx.x;
    if (i < NN * H3D) g_aggg[i] = 0.f;
    if (i < NN) {
        g_deg[i]   = 0.0f;
        g_amax[i]  = -3.0e38f;
        g_denom[i] = 0.f;
    }
    if (i < H3D) g_pool[i] = 0.f;
    if (i == 0)  g_is32 = 0;
}

// Detect whether edge_index buffer is int64 or int32.
// Interpret first EE slots as int64: true-int64 src values are all in [0,NN);
// an int32 buffer read as int64 packs two random indices (lo + hi*2^32) and
// goes out of range essentially immediately.
__global__ void k_detect(const long long* __restrict__ ei) {
    int e = blockIdx.x * blockDim.x + threadIdx.x;
    if (e >= EE) return;
    long long v = ei[e];
    if (v < 0 || v >= NN) atomicOr(&g_is32, 1);
}

// Materialize int32 src/dst arrays (self loops appended) and count degrees.
__global__ void k_convert(const void* __restrict__ ei_raw) {
    int e = blockIdx.x * blockDim.x + threadIdx.x;
    if (e >= ET) return;
    int s, d;
    if (e < EE) {
        if (g_is32) {
            const int* p = (const int*)ei_raw;
            s = p[e]; d = p[EE + e];
        } else {
            const long long* p = (const long long*)ei_raw;
            s = (int)p[e]; d = (int)p[EE + e];
        }
    } else {
        s = d = e - EE;
    }
    g_src[e] = s;
    g_dst[e] = d;
    atomicAdd(&g_deg[d], 1.0f);
}

__global__ void k_dinv() {
    int i = blockIdx.x * blockDim.x + threadIdx.x;
    if (i < NN) g_dinv[i] = rsqrtf(g_deg[i]);
}

__global__ void k_enorm() {
    int e = blockIdx.x * blockDim.x + threadIdx.x;
    if (e < ET) g_enorm[e] = g_dinv[g_src[e]] * g_dinv[g_dst[e]];
}

__global__ void k_setbias(float* __restrict__ agg, const float* __restrict__ b,
                          int total, int F) {
    int i = blockIdx.x * blockDim.x + threadIdx.x;
    if (i < total) agg[i] = b[i % F];
}

// ---------------- SGEMM: C = A(MxK) @ B(KxN), row-major ---------------------
// BM=128 BN=64 BK=16, 8x4 per thread, 256 threads, float4 loads/stores.
template <int BM, int BN, int BK, int TM, int TN>
__global__ __launch_bounds__(256)
void k_sgemm(const float* __restrict__ A, const float* __restrict__ B,
             float* __restrict__ C, int M, int N, int K) {
    __shared__ __align__(16) float As[BK][BM + 4];
    __shared__ __align__(16) float Bs[BK][BN];

    const int brow = blockIdx.y * BM;
    const int bcol = blockIdx.x * BN;
    const int tid  = threadIdx.x;
    const int tcol = tid % (BN / TN);
    const int trow = tid / (BN / TN);

    float acc[TM][TN];
#pragma unroll
    for (int i = 0; i < TM; i++)
#pragma unroll
        for (int j = 0; j < TN; j++) acc[i][j] = 0.f;

    for (int k0 = 0; k0 < K; k0 += BK) {
        // A tile: BM*BK/4 float4 loads, transposed into As[k][m]
#pragma unroll
        for (int i = tid; i < BM * BK / 4; i += 256) {
            int m  = i / (BK / 4);
            int kq = (i % (BK / 4)) * 4;
            int gm = brow + m;
            float4 v = make_float4(0.f, 0.f, 0.f, 0.f);
            if (gm < M)
                v = *reinterpret_cast<const float4*>(&A[(size_t)gm * K + k0 + kq]);
            As[kq + 0][m] = v.x;
            As[kq + 1][m] = v.y;
            As[kq + 2][m] = v.z;
            As[kq + 3][m] = v.w;
        }
        // B tile: BK*BN/4 float4 loads
#pragma unroll
        for (int i = tid; i < BK * BN / 4; i += 256) {
            int k  = i / (BN / 4);
            int nq = (i % (BN / 4)) * 4;
            int gn = bcol + nq;
            float4 v;
            if (gn + 3 < N) {
                v = *reinterpret_cast<const float4*>(&B[(size_t)(k0 + k) * N + gn]);
            } else {
                v.x = (gn + 0 < N) ? B[(size_t)(k0 + k) * N + gn + 0] : 0.f;
                v.y = (gn + 1 < N) ? B[(size_t)(k0 + k) * N + gn + 1] : 0.f;
                v.z = (gn + 2 < N) ? B[(size_t)(k0 + k) * N + gn + 2] : 0.f;
                v.w = (gn + 3 < N) ? B[(size_t)(k0 + k) * N + gn + 3] : 0.f;
            }
            *reinterpret_cast<float4*>(&Bs[k][nq]) = v;
        }
        __syncthreads();
#pragma unroll
        for (int k = 0; k < BK; k++) {
            float a[TM], b[TN];
#pragma unroll
            for (int i = 0; i < TM; i++) a[i] = As[k][trow * TM + i];
#pragma unroll
            for (int j = 0; j < TN; j++) b[j] = Bs[k][tcol * TN + j];
#pragma unroll
            for (int i = 0; i < TM; i++)
#pragma unroll
                for (int j = 0; j < TN; j++) acc[i][j] = fmaf(a[i], b[j], acc[i][j]);
        }
        __syncthreads();
    }
#pragma unroll
    for (int i = 0; i < TM; i++) {
        int gm = brow + trow * TM + i;
        if (gm >= M) continue;
        int gn = bcol + tcol * TN;
        if (TN == 4 && gn + 3 < N) {
            float4 v = make_float4(acc[i][0], acc[i][1], acc[i][2], acc[i][3]);
            *reinterpret_cast<float4*>(&C[(size_t)gm * N + gn]) = v;
        } else {
#pragma unroll
            for (int j = 0; j < TN; j++)
                if (gn + j < N) C[(size_t)gm * N + gn + j] = acc[i][j];
        }
    }
}

// ---------------- GCN aggregation: agg[dst] += xw[src]*norm -----------------
__global__ void k_gcn_agg(const float* __restrict__ xw,
                          float* __restrict__ agg, int F) {
    const int f4  = F >> 2;
    const int tot = ET * f4;
    int gid = blockIdx.x * blockDim.x + threadIdx.x;
    if (gid >= tot) return;
    int e = gid / f4;
    int f = (gid - e * f4) << 2;
    int s = g_src[e], d = g_dst[e];
    float nrm = g_enorm[e];
    float4 v = *reinterpret_cast<const float4*>(&xw[(size_t)s * F + f]);
    float* o = &agg[(size_t)d * F + f];
    atomicAdd(o + 0, v.x * nrm);
    atomicAdd(o + 1, v.y * nrm);
    atomicAdd(o + 2, v.z * nrm);
    atomicAdd(o + 3, v.w * nrm);
}

// ---------------- LayerNorm + ReLU (warp per row) ---------------------------
__global__ void k_ln_relu(const float* __restrict__ in, const float* __restrict__ g,
                          const float* __restrict__ b, float* __restrict__ out, int F) {
    int warp = (blockIdx.x * blockDim.x + threadIdx.x) >> 5;
    int lane = threadIdx.x & 31;
    if (warp >= NN) return;
    const float* row = in + (size_t)warp * F;
    float s = 0.f, s2 = 0.f;
    for (int f = lane; f < F; f += 32) {
        float v = row[f];
        s += v; s2 += v * v;
    }
#pragma unroll
    for (int o = 16; o; o >>= 1) {
        s  += __shfl_xor_sync(0xffffffffu, s,  o);
        s2 += __shfl_xor_sync(0xffffffffu, s2, o);
    }
    float mu  = s / F;
    float var = s2 / F - mu * mu;
    float inv = rsqrtf(var + LN_EPS);
    float* orow = out + (size_t)warp * F;
    for (int f = lane; f < F; f += 32) {
        float v = (row[f] - mu) * inv * g[f] + b[f];
        orow[f] = fmaxf(v, 0.f);
    }
}

// ---------------- GAT: xw = h@Wg, per-node att dots (warp per row) ----------
__global__ void k_gat_xw(const float* __restrict__ h, const float* __restrict__ Wg,
                         const float* __restrict__ asrc, const float* __restrict__ adst) {
    int row = (blockIdx.x * blockDim.x + threadIdx.x) >> 5;
    int c   = threadIdx.x & 31;
    if (row >= NN) return;
    float hv = h[(size_t)row * H3D + c];
    float o = 0.f;
#pragma unroll
    for (int k = 0; k < H3D; k++)
        o = fmaf(__shfl_sync(0xffffffffu, hv, k), Wg[k * H3D + c], o);
    g_xwg[(size_t)row * H3D + c] = o;
    float sa = o * asrc[c];
    float sd = o * adst[c];
#pragma unroll
    for (int off = 16; off; off >>= 1) {
        sa += __shfl_xor_sync(0xffffffffu, sa, off);
        sd += __shfl_xor_sync(0xffffffffu, sd, off);
    }
    if (c == 0) { g_as[row] = sa; g_ad[row] = sd; }
}

__device__ __forceinline__ float lrelu02(float a) {
    return a > 0.f ? a : 0.2f * a;
}

__device__ void atomicMaxFloat(float* addr, float value) {
    int* a = (int*)addr;
    int old = *a;
    while (__int_as_float(old) < value) {
        int assumed = old;
        old = atomicCAS(a, assumed, __float_as_int(value));
        if (old == assumed) break;
    }
}

__global__ void k_gat_amax() {
    int e = blockIdx.x * blockDim.x + threadIdx.x;
    if (e >= ET) return;
    int s = g_src[e], d = g_dst[e];
    float a = lrelu02(g_as[s] + g_ad[d]);
    atomicMaxFloat(&g_amax[d], a);
}

__global__ void k_gat_exp() {
    int e = blockIdx.x * blockDim.x + threadIdx.x;
    if (e >= ET) return;
    int s = g_src[e], d = g_dst[e];
    float a  = lrelu02(g_as[s] + g_ad[d]);
    float ev = expf(a - g_amax[d]);
    g_earr[e] = ev;
    atomicAdd(&g_denom[d], ev);
}

__global__ void k_gat_msg() {
    const int f4 = H3D >> 2;  // 8
    int gid = blockIdx.x * blockDim.x + threadIdx.x;
    if (gid >= ET * f4) return;
    int e = gid / f4;
    int f = (gid - e * f4) << 2;
    int s = g_src[e], d = g_dst[e];
    float coef = g_earr[e] / g_denom[d];
    float4 v = *reinterpret_cast<const float4*>(&g_xwg[(size_t)s * H3D + f]);
    float* o = &g_aggg[(size_t)d * H3D + f];
    atomicAdd(o + 0, v.x * coef);
    atomicAdd(o + 1, v.y * coef);
    atomicAdd(o + 2, v.z * coef);
    atomicAdd(o + 3, v.w * coef);
}

// ---------------- bias + ReLU + mean pool -----------------------------------
__global__ void k_pool(const float* __restrict__ bg) {
    const int NPB = 1024;
    __shared__ float sp[8][H3D];
    int f = threadIdx.x;       // 0..31
    int w = threadIdx.y;       // 0..7
    int base = blockIdx.x * NPB;
    float acc = 0.f;
    for (int nd = base + w; nd < base + NPB && nd < NN; nd += 8)
        acc += fmaxf(g_aggg[(size_t)nd * H3D + f] + bg[f], 0.f);
    sp[w][f] = acc;
    __syncthreads();
    if (w == 0) {
        float t = sp[0][f];
#pragma unroll
        for (int j = 1; j < 8; j++) t += sp[j][f];
        atomicAdd(&g_pool[f], t);
    }
}

__global__ void k_final(const float* __restrict__ fcw, const float* __restrict__ fcb,
                        float* __restrict__ out) {
    int k = threadIdx.x;  // 32 threads
    float p = g_pool[k] / (float)NN;
    float c0 = p * fcw[k * 2 + 0];
    float c1 = p * fcw[k * 2 + 1];
#pragma unroll
    for (int o = 16; o; o >>= 1) {
        c0 += __shfl_xor_sync(0xffffffffu, c0, o);
        c1 += __shfl_xor_sync(0xffffffffu, c1, o);
    }
    if (k == 0) {
        out[0] = c0 + fcb[0];
        out[1] = c1 + fcb[1];
    }
}

// ---------------- launch ----------------------------------------------------
static float* sym(const void* s) {
    void* p = nullptr;
    cudaGetSymbolAddress(&p, s);
    return (float*)p;
}

extern "C" void kernel_launch(void* const* d_in, const int* in_sizes, int n_in,
                              void* d_out, int out_size) {
    const float* x    = (const float*)d_in[0];
    const void*  ei   = d_in[1];                 // int64 or int32 (probed on device)
    const float* W1   = (const float*)d_in[2];
    const float* b1   = (const float*)d_in[3];
    const float* ln1g = (const float*)d_in[4];
    const float* ln1b = (const float*)d_in[5];
    const float* W2   = (const float*)d_in[6];
    const float* b2   = (const float*)d_in[7];
    const float* ln2g = (const float*)d_in[8];
    const float* ln2b = (const float*)d_in[9];
    const float* W3   = (const float*)d_in[10];
    const float* b3   = (const float*)d_in[11];
    const float* ln3g = (const float*)d_in[12];
    const float* ln3b = (const float*)d_in[13];
    const float* Wg   = (const float*)d_in[14];
    const float* atts = (const float*)d_in[15];
    const float* attd = (const float*)d_in[16];
    const float* bg   = (const float*)d_in[17];
    const float* fcw  = (const float*)d_in[18];
    const float* fcb  = (const float*)d_in[19];
    float* out = (float*)d_out;

    float* xw1  = sym(g_xw1);   float* agg1 = sym(g_agg1); float* h1 = sym(g_h1);
    float* xw2  = sym(g_xw2);   float* agg2 = sym(g_agg2); float* h2 = sym(g_h2);
    float* xw3  = sym(g_xw3);   float* agg3 = sym(g_agg3); float* h3 = sym(g_h3);

    const int T = 256;

    // init + edge prep + degree
    k_init<<<(NN * H3D + T - 1) / T, T>>>();
    k_detect<<<(EE + T - 1) / T, T>>>((const long long*)ei);
    k_convert<<<(ET + T - 1) / T, T>>>(ei);
    k_dinv<<<(NN + T - 1) / T, T>>>();
    k_enorm<<<(ET + T - 1) / T, T>>>();

    // ---- GCN layer 1 ----
    {
        dim3 grid(H1D / 64, (NN + 127) / 128);
        k_sgemm<128, 64, 16, 8, 4><<<grid, 256>>>(x, W1, xw1, NN, H1D, DIN);
    }
    k_setbias<<<(NN * H1D + T - 1) / T, T>>>(agg1, b1, NN * H1D, H1D);
    k_gcn_agg<<<(ET * (H1D / 4) + T - 1) / T, T>>>(xw1, agg1, H1D);
    k_ln_relu<<<(NN * 32 + T - 1) / T, T>>>(agg1, ln1g, ln1b, h1, H1D);

    // ---- GCN layer 2 ----
    {
        dim3 grid(H2D / 64, (NN + 127) / 128);
        k_sgemm<128, 64, 16, 8, 4><<<grid, 256>>>(h1, W2, xw2, NN, H2D, H1D);
    }
    k_setbias<<<(NN * H2D + T - 1) / T, T>>>(agg2, b2, NN * H2D, H2D);
    k_gcn_agg<<<(ET * (H2D / 4) + T - 1) / T, T>>>(xw2, agg2, H2D);
    k_ln_relu<<<(NN * 32 + T - 1) / T, T>>>(agg2, ln2g, ln2b, h2, H2D);

    // ---- GCN layer 3 ----
    {
        dim3 grid((H3D + 63) / 64, (NN + 127) / 128);
        k_sgemm<128, 64, 16, 8, 4><<<grid, 256>>>(h2, W3, xw3, NN, H3D, H2D);
    }
    k_setbias<<<(NN * H3D + T - 1) / T, T>>>(agg3, b3, NN * H3D, H3D);
    k_gcn_agg<<<(ET * (H3D / 4) + T - 1) / T, T>>>(xw3, agg3, H3D);
    k_ln_relu<<<(NN * 32 + T - 1) / T, T>>>(agg3, ln3g, ln3b, h3, H3D);

    // ---- GAT ----
    k_gat_xw<<<(NN * 32 + T - 1) / T, T>>>(h3, Wg, atts, attd);
    k_gat_amax<<<(ET + T - 1) / T, T>>>();
    k_gat_exp<<<(ET + T - 1) / T, T>>>();
    k_gat_msg<<<(ET * (H3D / 4) + T - 1) / T, T>>>();

    // ---- pool + fc ----
    k_pool<<<(NN + 1023) / 1024, dim3(32, 8)>>>(bg);
    k_final<<<1, 32>>>(fcw, fcb, out);
}

// round 4
// speedup vs baseline: 1.3534x; 1.3534x over previous
#include <cuda_runtime.h>
#include <cstdint>

#define NN   20000
#define EE   320000
#define DIN  2048
#define H1D  512
#define H2D  128
#define H3D  32
#define LN_EPS 1e-5f
#define ET   (EE + NN)   // edges incl. self loops

// ---------------- scratch (static device globals; no allocation) -------------
__device__ __align__(16) float g_xw1[NN * H1D];
__device__ __align__(16) float g_agg1[NN * H1D];
__device__ __align__(16) float g_h1[NN * H1D];
__device__ __align__(16) float g_xw2[NN * H2D];
__device__ __align__(16) float g_agg2[NN * H2D];
__device__ __align__(16) float g_h2[NN * H2D];
__device__ __align__(16) float g_xw3[NN * H3D];
__device__ __align__(16) float g_agg3[NN * H3D];
__device__ __align__(16) float g_h3[NN * H3D];
__device__ __align__(16) float g_xwg[NN * H3D];
__device__ __align__(16) float g_aggg[NN * H3D];
__device__ float g_deg[NN];
__device__ float g_dinv[NN];
__device__ float g_as[NN];
__device__ float g_ad[NN];
__device__ float g_amax[NN];
__device__ float g_denom[NN];
__device__ float g_earr[ET];
__device__ float g_enorm[ET];
__device__ int   g_src[ET];
__device__ int   g_dst[ET];
__device__ float g_pool[H3D];
__device__ int   g_is32;

// ---------------- init ------------------------------------------------------
__global__ void k_init() {
    int i = blockIdx.x * blockDim.x + threadIdx.x;
    if (i < NN * H3D) g_aggg[i] = 0.f;
    if (i < NN) {
        g_deg[i]   = 0.0f;
        g_amax[i]  = -3.0e38f;
        g_denom[i] = 0.f;
    }
    if (i < H3D) g_pool[i] = 0.f;
    if (i == 0)  g_is32 = 0;
}

// Detect whether edge_index buffer is int64 or int32 (device-side probe).
__global__ void k_detect(const long long* __restrict__ ei) {
    int e = blockIdx.x * blockDim.x + threadIdx.x;
    if (e >= EE) return;
    long long v = ei[e];
    if (v < 0 || v >= NN) atomicOr(&g_is32, 1);
}

// Materialize int32 src/dst arrays (self loops appended) and count degrees.
__global__ void k_convert(const void* __restrict__ ei_raw) {
    int e = blockIdx.x * blockDim.x + threadIdx.x;
    if (e >= ET) return;
    int s, d;
    if (e < EE) {
        if (g_is32) {
            const int* p = (const int*)ei_raw;
            s = p[e]; d = p[EE + e];
        } else {
            const long long* p = (const long long*)ei_raw;
            s = (int)p[e]; d = (int)p[EE + e];
        }
    } else {
        s = d = e - EE;
    }
    g_src[e] = s;
    g_dst[e] = d;
    atomicAdd(&g_deg[d], 1.0f);
}

__global__ void k_dinv() {
    int i = blockIdx.x * blockDim.x + threadIdx.x;
    if (i < NN) g_dinv[i] = rsqrtf(g_deg[i]);
}

__global__ void k_enorm() {
    int e = blockIdx.x * blockDim.x + threadIdx.x;
    if (e < ET) g_enorm[e] = g_dinv[g_src[e]] * g_dinv[g_dst[e]];
}

__global__ void k_setbias(float* __restrict__ agg, const float* __restrict__ b,
                          int total, int F) {
    int i = blockIdx.x * blockDim.x + threadIdx.x;
    if (i < total) agg[i] = b[i % F];
}

// ---------------- tf32 tensor-core GEMM with B-split (3xtf32-lite) ----------
// C = A(MxK) @ B(KxN), fp32 in/out.  B is split B = Bhi + Blo (both tf32) so
// weight rounding error is second-order; A is rounded once to tf32 (random
// error, cancels in the final mean-pool).
// Tiles: BM=128, BN=64, BK=32. 8 warps: warp_m = w>>1 (4), warp_n = w&1 (2).
// Each warp computes 32x32 via 2(m) x 4(n) m16n8k8 mma tiles, hi+lo chains.

__device__ __forceinline__ uint32_t f2tf32(float x) {
    uint32_t r;
    asm("cvt.rna.tf32.f32 %0, %1;" : "=r"(r) : "f"(x));
    return r;
}

__device__ __forceinline__ void mma_tf32(float (&d)[4], const uint32_t (&a)[4],
                                         const uint32_t (&b)[2]) {
    asm volatile(
        "mma.sync.aligned.m16n8k8.row.col.f32.tf32.tf32.f32 "
        "{%0,%1,%2,%3}, {%4,%5,%6,%7}, {%8,%9}, {%0,%1,%2,%3};\n"
        : "+f"(d[0]), "+f"(d[1]), "+f"(d[2]), "+f"(d[3])
        : "r"(a[0]), "r"(a[1]), "r"(a[2]), "r"(a[3]), "r"(b[0]), "r"(b[1]));
}

#define GBM 128
#define GBN 64
#define GBK 32

__global__ __launch_bounds__(256)
void k_tf32gemm(const float* __restrict__ A, const float* __restrict__ B,
                float* __restrict__ C, int M, int N, int K) {
    __shared__ uint32_t As[GBM][GBK + 4];      // conflict-free for frag reads
    __shared__ uint32_t Bh[GBK][GBN + 8];
    __shared__ uint32_t Bl[GBK][GBN + 8];

    const int tid  = threadIdx.x;
    const int lane = tid & 31;
    const int warp = tid >> 5;
    const int wm   = warp >> 1;       // 0..3
    const int wn   = warp & 1;        // 0..1
    const int gid  = lane >> 2;       // 0..7
    const int tig  = lane & 3;        // 0..3

    const int brow = blockIdx.y * GBM;
    const int bcol = blockIdx.x * GBN;

    float acc[2][4][4];
#pragma unroll
    for (int i = 0; i < 2; i++)
#pragma unroll
        for (int j = 0; j < 4; j++)
#pragma unroll
            for (int r = 0; r < 4; r++) acc[i][j][r] = 0.f;

    for (int k0 = 0; k0 < K; k0 += GBK) {
        // ---- load A tile: 128x32 fp32 -> tf32, 4 float4 per thread ----
#pragma unroll
        for (int it = 0; it < 4; it++) {
            int idx = tid + it * 256;          // 0..1023
            int m   = idx >> 3;                // /8
            int kq  = (idx & 7) << 2;          // *4
            int gm  = brow + m;
            float4 v = make_float4(0.f, 0.f, 0.f, 0.f);
            if (gm < M)
                v = *reinterpret_cast<const float4*>(&A[(size_t)gm * K + k0 + kq]);
            As[m][kq + 0] = f2tf32(v.x);
            As[m][kq + 1] = f2tf32(v.y);
            As[m][kq + 2] = f2tf32(v.z);
            As[m][kq + 3] = f2tf32(v.w);
        }
        // ---- load B tile: 32x64 fp32 -> hi/lo tf32, 2 float4 per thread ----
#pragma unroll
        for (int it = 0; it < 2; it++) {
            int idx = tid + it * 256;          // 0..511
            int k   = idx >> 4;                // /16
            int nq  = (idx & 15) << 2;         // *4
            int gn  = bcol + nq;
            float4 v = make_float4(0.f, 0.f, 0.f, 0.f);
            if (gn + 3 < N) {
                v = *reinterpret_cast<const float4*>(&B[(size_t)(k0 + k) * N + gn]);
            } else {
                if (gn + 0 < N) v.x = B[(size_t)(k0 + k) * N + gn + 0];
                if (gn + 1 < N) v.y = B[(size_t)(k0 + k) * N + gn + 1];
                if (gn + 2 < N) v.z = B[(size_t)(k0 + k) * N + gn + 2];
                if (gn + 3 < N) v.w = B[(size_t)(k0 + k) * N + gn + 3];
            }
            float f[4] = {v.x, v.y, v.z, v.w};
#pragma unroll
            for (int j = 0; j < 4; j++) {
                uint32_t hi = f2tf32(f[j]);
                Bh[k][nq + j] = hi;
                Bl[k][nq + j] = f2tf32(f[j] - __uint_as_float(hi));
            }
        }
        __syncthreads();

#pragma unroll
        for (int ks = 0; ks < 4; ks++) {
            const int kk = ks * 8;
            uint32_t af[2][4];
#pragma unroll
            for (int ms = 0; ms < 2; ms++) {
                int m0 = wm * 32 + ms * 16;
                af[ms][0] = As[m0 + gid    ][kk + tig];
                af[ms][1] = As[m0 + gid + 8][kk + tig];
                af[ms][2] = As[m0 + gid    ][kk + tig + 4];
                af[ms][3] = As[m0 + gid + 8][kk + tig + 4];
            }
#pragma unroll
            for (int ns = 0; ns < 4; ns++) {
                int n0 = wn * 32 + ns * 8;
                uint32_t bh[2], bl[2];
                bh[0] = Bh[kk + tig    ][n0 + gid];
                bh[1] = Bh[kk + tig + 4][n0 + gid];
                bl[0] = Bl[kk + tig    ][n0 + gid];
                bl[1] = Bl[kk + tig + 4][n0 + gid];
#pragma unroll
                for (int ms = 0; ms < 2; ms++) {
                    mma_tf32(acc[ms][ns], af[ms], bh);
                    mma_tf32(acc[ms][ns], af[ms], bl);
                }
            }
        }
        __syncthreads();
    }

    // ---- store C ----
#pragma unroll
    for (int ms = 0; ms < 2; ms++) {
#pragma unroll
        for (int ns = 0; ns < 4; ns++) {
            int row = brow + wm * 32 + ms * 16 + gid;
            int col = bcol + wn * 32 + ns * 8 + tig * 2;
            if (col < N) {
                if (row < M) {
                    C[(size_t)row * N + col]     = acc[ms][ns][0];
                    C[(size_t)row * N + col + 1] = acc[ms][ns][1];
                }
                if (row + 8 < M) {
                    C[(size_t)(row + 8) * N + col]     = acc[ms][ns][2];
                    C[(size_t)(row + 8) * N + col + 1] = acc[ms][ns][3];
                }
            }
        }
    }
}

// ---------------- GCN aggregation: agg[dst] += xw[src]*norm -----------------
__global__ void k_gcn_agg(const float* __restrict__ xw,
                          float* __restrict__ agg, int F) {
    const int f4  = F >> 2;
    const int tot = ET * f4;
    int gid = blockIdx.x * blockDim.x + threadIdx.x;
    if (gid >= tot) return;
    int e = gid / f4;
    int f = (gid - e * f4) << 2;
    int s = g_src[e], d = g_dst[e];
    float nrm = g_enorm[e];
    float4 v = *reinterpret_cast<const float4*>(&xw[(size_t)s * F + f]);
    float* o = &agg[(size_t)d * F + f];
    atomicAdd(o + 0, v.x * nrm);
    atomicAdd(o + 1, v.y * nrm);
    atomicAdd(o + 2, v.z * nrm);
    atomicAdd(o + 3, v.w * nrm);
}

// ---------------- LayerNorm + ReLU (warp per row) ---------------------------
__global__ void k_ln_relu(const float* __restrict__ in, const float* __restrict__ g,
                          const float* __restrict__ b, float* __restrict__ out, int F) {
    int warp = (blockIdx.x * blockDim.x + threadIdx.x) >> 5;
    int lane = threadIdx.x & 31;
    if (warp >= NN) return;
    const float* row = in + (size_t)warp * F;
    float s = 0.f, s2 = 0.f;
    for (int f = lane; f < F; f += 32) {
        float v = row[f];
        s += v; s2 += v * v;
    }
#pragma unroll
    for (int o = 16; o; o >>= 1) {
        s  += __shfl_xor_sync(0xffffffffu, s,  o);
        s2 += __shfl_xor_sync(0xffffffffu, s2, o);
    }
    float mu  = s / F;
    float var = s2 / F - mu * mu;
    float inv = rsqrtf(var + LN_EPS);
    float* orow = out + (size_t)warp * F;
    for (int f = lane; f < F; f += 32) {
        float v = (row[f] - mu) * inv * g[f] + b[f];
        orow[f] = fmaxf(v, 0.f);
    }
}

// ---------------- GAT: xw = h@Wg, per-node att dots (warp per row) ----------
__global__ void k_gat_xw(const float* __restrict__ h, const float* __restrict__ Wg,
                         const float* __restrict__ asrc, const float* __restrict__ adst) {
    int row = (blockIdx.x * blockDim.x + threadIdx.x) >> 5;
    int c   = threadIdx.x & 31;
    if (row >= NN) return;
    float hv = h[(size_t)row * H3D + c];
    float o = 0.f;
#pragma unroll
    for (int k = 0; k < H3D; k++)
        o = fmaf(__shfl_sync(0xffffffffu, hv, k), Wg[k * H3D + c], o);
    g_xwg[(size_t)row * H3D + c] = o;
    float sa = o * asrc[c];
    float sd = o * adst[c];
#pragma unroll
    for (int off = 16; off; off >>= 1) {
        sa += __shfl_xor_sync(0xffffffffu, sa, off);
        sd += __shfl_xor_sync(0xffffffffu, sd, off);
    }
    if (c == 0) { g_as[row] = sa; g_ad[row] = sd; }
}

__device__ __forceinline__ float lrelu02(float a) {
    return a > 0.f ? a : 0.2f * a;
}

__device__ void atomicMaxFloat(float* addr, float value) {
    int* a = (int*)addr;
    int old = *a;
    while (__int_as_float(old) < value) {
        int assumed = old;
        old = atomicCAS(a, assumed, __float_as_int(value));
        if (old == assumed) break;
    }
}

__global__ void k_gat_amax() {
    int e = blockIdx.x * blockDim.x + threadIdx.x;
    if (e >= ET) return;
    int s = g_src[e], d = g_dst[e];
    float a = lrelu02(g_as[s] + g_ad[d]);
    atomicMaxFloat(&g_amax[d], a);
}

__global__ void k_gat_exp() {
    int e = blockIdx.x * blockDim.x + threadIdx.x;
    if (e >= ET) return;
    int s = g_src[e], d = g_dst[e];
    float a  = lrelu02(g_as[s] + g_ad[d]);
    float ev = expf(a - g_amax[d]);
    g_earr[e] = ev;
    atomicAdd(&g_denom[d], ev);
}

__global__ void k_gat_msg() {
    const int f4 = H3D >> 2;  // 8
    int gid = blockIdx.x * blockDim.x + threadIdx.x;
    if (gid >= ET * f4) return;
    int e = gid / f4;
    int f = (gid - e * f4) << 2;
    int s = g_src[e], d = g_dst[e];
    float coef = g_earr[e] / g_denom[d];
    float4 v = *reinterpret_cast<const float4*>(&g_xwg[(size_t)s * H3D + f]);
    float* o = &g_aggg[(size_t)d * H3D + f];
    atomicAdd(o + 0, v.x * coef);
    atomicAdd(o + 1, v.y * coef);
    atomicAdd(o + 2, v.z * coef);
    atomicAdd(o + 3, v.w * coef);
}

// ---------------- bias + ReLU + mean pool -----------------------------------
__global__ void k_pool(const float* __restrict__ bg) {
    const int NPB = 1024;
    __shared__ float sp[8][H3D];
    int f = threadIdx.x;       // 0..31
    int w = threadIdx.y;       // 0..7
    int base = blockIdx.x * NPB;
    float acc = 0.f;
    for (int nd = base + w; nd < base + NPB && nd < NN; nd += 8)
        acc += fmaxf(g_aggg[(size_t)nd * H3D + f] + bg[f], 0.f);
    sp[w][f] = acc;
    __syncthreads();
    if (w == 0) {
        float t = sp[0][f];
#pragma unroll
        for (int j = 1; j < 8; j++) t += sp[j][f];
        atomicAdd(&g_pool[f], t);
    }
}

__global__ void k_final(const float* __restrict__ fcw, const float* __restrict__ fcb,
                        float* __restrict__ out) {
    int k = threadIdx.x;  // 32 threads
    float p = g_pool[k] / (float)NN;
    float c0 = p * fcw[k * 2 + 0];
    float c1 = p * fcw[k * 2 + 1];
#pragma unroll
    for (int o = 16; o; o >>= 1) {
        c0 += __shfl_xor_sync(0xffffffffu, c0, o);
        c1 += __shfl_xor_sync(0xffffffffu, c1, o);
    }
    if (k == 0) {
        out[0] = c0 + fcb[0];
        out[1] = c1 + fcb[1];
    }
}

// ---------------- launch ----------------------------------------------------
static float* sym(const void* s) {
    void* p = nullptr;
    cudaGetSymbolAddress(&p, s);
    return (float*)p;
}

extern "C" void kernel_launch(void* const* d_in, const int* in_sizes, int n_in,
                              void* d_out, int out_size) {
    const float* x    = (const float*)d_in[0];
    const void*  ei   = d_in[1];                 // int64 or int32 (probed on device)
    const float* W1   = (const float*)d_in[2];
    const float* b1   = (const float*)d_in[3];
    const float* ln1g = (const float*)d_in[4];
    const float* ln1b = (const float*)d_in[5];
    const float* W2   = (const float*)d_in[6];
    const float* b2   = (const float*)d_in[7];
    const float* ln2g = (const float*)d_in[8];
    const float* ln2b = (const float*)d_in[9];
    const float* W3   = (const float*)d_in[10];
    const float* b3   = (const float*)d_in[11];
    const float* ln3g = (const float*)d_in[12];
    const float* ln3b = (const float*)d_in[13];
    const float* Wg   = (const float*)d_in[14];
    const float* atts = (const float*)d_in[15];
    const float* attd = (const float*)d_in[16];
    const float* bg   = (const float*)d_in[17];
    const float* fcw  = (const float*)d_in[18];
    const float* fcb  = (const float*)d_in[19];
    float* out = (float*)d_out;

    float* xw1  = sym(g_xw1);   float* agg1 = sym(g_agg1); float* h1 = sym(g_h1);
    float* xw2  = sym(g_xw2);   float* agg2 = sym(g_agg2); float* h2 = sym(g_h2);
    float* xw3  = sym(g_xw3);   float* agg3 = sym(g_agg3); float* h3 = sym(g_h3);

    const int T = 256;
    const int MGRID = (NN + GBM - 1) / GBM;   // 157

    // init + edge prep + degree
    k_init<<<(NN * H3D + T - 1) / T, T>>>();
    k_detect<<<(EE + T - 1) / T, T>>>((const long long*)ei);
    k_convert<<<(ET + T - 1) / T, T>>>(ei);
    k_dinv<<<(NN + T - 1) / T, T>>>();
    k_enorm<<<(ET + T - 1) / T, T>>>();

    // ---- GCN layer 1 ----
    k_tf32gemm<<<dim3(H1D / GBN, MGRID), 256>>>(x, W1, xw1, NN, H1D, DIN);
    k_setbias<<<(NN * H1D + T - 1) / T, T>>>(agg1, b1, NN * H1D, H1D);
    k_gcn_agg<<<(ET * (H1D / 4) + T - 1) / T, T>>>(xw1, agg1, H1D);
    k_ln_relu<<<(NN * 32 + T - 1) / T, T>>>(agg1, ln1g, ln1b, h1, H1D);

    // ---- GCN layer 2 ----
    k_tf32gemm<<<dim3(H2D / GBN, MGRID), 256>>>(h1, W2, xw2, NN, H2D, H1D);
    k_setbias<<<(NN * H2D + T - 1) / T, T>>>(agg2, b2, NN * H2D, H2D);
    k_gcn_agg<<<(ET * (H2D / 4) + T - 1) / T, T>>>(xw2, agg2, H2D);
    k_ln_relu<<<(NN * 32 + T - 1) / T, T>>>(agg2, ln2g, ln2b, h2, H2D);

    // ---- GCN layer 3 ----
    k_tf32gemm<<<dim3((H3D + GBN - 1) / GBN, MGRID), 256>>>(h2, W3, xw3, NN, H3D, H2D);
    k_setbias<<<(NN * H3D + T - 1) / T, T>>>(agg3, b3, NN * H3D, H3D);
    k_gcn_agg<<<(ET * (H3D / 4) + T - 1) / T, T>>>(xw3, agg3, H3D);
    k_ln_relu<<<(NN * 32 + T - 1) / T, T>>>(agg3, ln3g, ln3b, h3, H3D);

    // ---- GAT ----
    k_gat_xw<<<(NN * 32 + T - 1) / T, T>>>(h3, Wg, atts, attd);
    k_gat_amax<<<(ET + T - 1) / T, T>>>();
    k_gat_exp<<<(ET + T - 1) / T, T>>>();
    k_gat_msg<<<(ET * (H3D / 4) + T - 1) / T, T>>>();

    // ---- pool + fc ----
    k_pool<<<(NN + 1023) / 1024, dim3(32, 8)>>>(bg);
    k_final<<<1, 32>>>(fcw, fcb, out);
}

// round 7
// speedup vs baseline: 1.6811x; 1.2421x over previous
#include <cuda_runtime.h>
#include <cstdint>

#define NN   20000
#define EE   320000
#define DIN  2048
#define H1D  512
#define H2D  128
#define H3D  32
#define LN_EPS 1e-5f
#define ET   (EE + NN)   // edges incl. self loops

// ---------------- scratch (static device globals; no allocation) -------------
__device__ __align__(16) float g_xw1[NN * H1D];
__device__ __align__(16) float g_agg1[NN * H1D];
__device__ __align__(16) float g_h1[NN * H1D];
__device__ __align__(16) float g_xw2[NN * H2D];
__device__ __align__(16) float g_agg2[NN * H2D];
__device__ __align__(16) float g_h2[NN * H2D];
__device__ __align__(16) float g_xw3[NN * H3D];
__device__ __align__(16) float g_agg3[NN * H3D];
__device__ __align__(16) float g_h3[NN * H3D];
__device__ __align__(16) float g_xwg[NN * H3D];
__device__ __align__(16) float g_aggg[NN * H3D];
__device__ float g_deg[NN];
__device__ float g_dinv[NN];
__device__ float g_as[NN];
__device__ float g_ad[NN];
__device__ float g_amax[NN];
__device__ float g_denom[NN];
__device__ float g_earr[ET];
__device__ float g_enorm[ET];
__device__ int   g_src[ET];
__device__ int   g_dst[ET];
__device__ float g_pool[H3D];
__device__ int   g_is32;

// ---------------- init ------------------------------------------------------
__global__ void k_init() {
    int i = blockIdx.x * blockDim.x + threadIdx.x;
    if (i < NN * H3D) g_aggg[i] = 0.f;
    if (i < NN) {
        g_deg[i]   = 0.0f;
        g_amax[i]  = -3.0e38f;
        g_denom[i] = 0.f;
    }
    if (i < H3D) g_pool[i] = 0.f;
    if (i == 0)  g_is32 = 0;
}

// Detect whether edge_index buffer is int64 or int32 (device-side probe).
__global__ void k_detect(const long long* __restrict__ ei) {
    int e = blockIdx.x * blockDim.x + threadIdx.x;
    if (e >= EE) return;
    long long v = ei[e];
    if (v < 0 || v >= NN) atomicOr(&g_is32, 1);
}

// Materialize int32 src/dst arrays (self loops appended) and count degrees.
__global__ void k_convert(const void* __restrict__ ei_raw) {
    int e = blockIdx.x * blockDim.x + threadIdx.x;
    if (e >= ET) return;
    int s, d;
    if (e < EE) {
        if (g_is32) {
            const int* p = (const int*)ei_raw;
            s = p[e]; d = p[EE + e];
        } else {
            const long long* p = (const long long*)ei_raw;
            s = (int)p[e]; d = (int)p[EE + e];
        }
    } else {
        s = d = e - EE;
    }
    g_src[e] = s;
    g_dst[e] = d;
    atomicAdd(&g_deg[d], 1.0f);
}

__global__ void k_dinv() {
    int i = blockIdx.x * blockDim.x + threadIdx.x;
    if (i < NN) g_dinv[i] = rsqrtf(g_deg[i]);
}

__global__ void k_enorm() {
    int e = blockIdx.x * blockDim.x + threadIdx.x;
    if (e < ET) g_enorm[e] = g_dinv[g_src[e]] * g_dinv[g_dst[e]];
}

__global__ void k_setbias(float* __restrict__ agg, const float* __restrict__ b,
                          int total, int F) {
    int i = blockIdx.x * blockDim.x + threadIdx.x;
    if (i < total) agg[i] = b[i % F];
}

// ============ pipelined tf32 tensor-core GEMM, B hi/lo split ================
// C = A(MxK) @ B(KxN) fp32.  BM=128 BN=128 BK=32, 512 threads (16 warps),
// warp tile 32x32 (wm=warp>>2, wn=warp&3).  cp.async double-buffered fp32
// staging; tf32 conversion (A) and hi/lo split (B) at fragment-load time.

__device__ __forceinline__ uint32_t f2tf32(float x) {
    uint32_t r;
    asm("cvt.rna.tf32.f32 %0, %1;" : "=r"(r) : "f"(x));
    return r;
}

__device__ __forceinline__ void mma_tf32(float (&d)[4], const uint32_t (&a)[4],
                                         const uint32_t (&b)[2]) {
    asm volatile(
        "mma.sync.aligned.m16n8k8.row.col.f32.tf32.tf32.f32 "
        "{%0,%1,%2,%3}, {%4,%5,%6,%7}, {%8,%9}, {%0,%1,%2,%3};\n"
        : "+f"(d[0]), "+f"(d[1]), "+f"(d[2]), "+f"(d[3])
        : "r"(a[0]), "r"(a[1]), "r"(a[2]), "r"(a[3]), "r"(b[0]), "r"(b[1]));
}

__device__ __forceinline__ void cp16(uint32_t dst, const void* src, bool pred) {
    int sz = pred ? 16 : 0;
    asm volatile("cp.async.ca.shared.global [%0], [%1], 16, %2;\n"
                 :: "r"(dst), "l"(src), "r"(sz));
}
__device__ __forceinline__ void cp_commit() {
    asm volatile("cp.async.commit_group;\n");
}
template <int NMAX>
__device__ __forceinline__ void cp_wait() {
    asm volatile("cp.async.wait_group %0;\n" :: "n"(NMAX));
}

// 16B vector reduction (fire-and-forget), sm_90+
__device__ __forceinline__ void red_add_v4(float* addr, float x, float y,
                                           float z, float w) {
    asm volatile("red.global.add.v4.f32 [%0], {%1,%2,%3,%4};\n"
                 :: "l"(addr), "f"(x), "f"(y), "f"(z), "f"(w) : "memory");
}

#define GBM 128
#define GBN 128
#define GBK 32
#define ASTRIDE 36          // 128 rows x 36 floats (pad 4): frag reads conflict-free
#define BSTRIDE 136         // 32 rows x 136 floats (pad 8): frag reads conflict-free
#define A_SZ (GBM * ASTRIDE)            // 4608 floats
#define B_SZ (GBK * BSTRIDE)            // 4352 floats
#define BUF_SZ (A_SZ + B_SZ)            // 8960 floats
#define GEMM_SMEM_BYTES (2 * BUF_SZ * 4)  // 71680 B

__global__ __launch_bounds__(512)
void k_gemm(const float* __restrict__ A, const float* __restrict__ B,
            float* __restrict__ C, int M, int N, int K) {
    extern __shared__ float smem[];
    const uint32_t sbase = (uint32_t)__cvta_generic_to_shared(smem);

    const int tid  = threadIdx.x;
    const int lane = tid & 31;
    const int warp = tid >> 5;
    const int wm   = warp >> 2;       // 0..3
    const int wn   = warp & 3;        // 0..3
    const int gid  = lane >> 2;       // 0..7
    const int tig  = lane & 3;        // 0..3

    const int brow = blockIdx.y * GBM;
    const int bcol = blockIdx.x * GBN;

    const int a_m0 = (tid + 0)   >> 3, a_c0 = (tid + 0)   & 7;
    const int a_m1 = (tid + 512) >> 3, a_c1 = (tid + 512) & 7;
    const int b_k0 = (tid + 0)   >> 5, b_c0 = (tid + 0)   & 31;
    const int b_k1 = (tid + 512) >> 5, b_c1 = (tid + 512) & 31;

    const int nt = K / GBK;

    auto issue = [&](int it) {
        const int k0  = it * GBK;
        const uint32_t abase = sbase + ((it & 1) * BUF_SZ) * 4;
        const uint32_t bbase = abase + A_SZ * 4;
        {
            int gm = brow + a_m0;
            cp16(abase + (a_m0 * ASTRIDE + a_c0 * 4) * 4,
                 A + (size_t)gm * K + k0 + a_c0 * 4, gm < M);
            gm = brow + a_m1;
            cp16(abase + (a_m1 * ASTRIDE + a_c1 * 4) * 4,
                 A + (size_t)gm * K + k0 + a_c1 * 4, gm < M);
        }
        {
            int gn = bcol + b_c0 * 4;
            cp16(bbase + (b_k0 * BSTRIDE + b_c0 * 4) * 4,
                 B + (size_t)(k0 + b_k0) * N + gn, gn < N);
            gn = bcol + b_c1 * 4;
            cp16(bbase + (b_k1 * BSTRIDE + b_c1 * 4) * 4,
                 B + (size_t)(k0 + b_k1) * N + gn, gn < N);
        }
        cp_commit();
    };

    float acc[2][4][4];
#pragma unroll
    for (int i = 0; i < 2; i++)
#pragma unroll
        for (int j = 0; j < 4; j++)
#pragma unroll
            for (int r = 0; r < 4; r++) acc[i][j][r] = 0.f;

    issue(0);

    for (int it = 0; it < nt; it++) {
        if (it + 1 < nt) { issue(it + 1); cp_wait<1>(); }
        else             { cp_wait<0>(); }
        __syncthreads();

        const float* As = smem + (it & 1) * BUF_SZ;
        const float* Bs = As + A_SZ;

#pragma unroll
        for (int ks = 0; ks < 4; ks++) {
            const int kk = ks * 8;
            uint32_t af[2][4];
#pragma unroll
            for (int ms = 0; ms < 2; ms++) {
                const int m0 = wm * 32 + ms * 16;
                af[ms][0] = f2tf32(As[(m0 + gid)     * ASTRIDE + kk + tig]);
                af[ms][1] = f2tf32(As[(m0 + gid + 8) * ASTRIDE + kk + tig]);
                af[ms][2] = f2tf32(As[(m0 + gid)     * ASTRIDE + kk + tig + 4]);
                af[ms][3] = f2tf32(As[(m0 + gid + 8) * ASTRIDE + kk + tig + 4]);
            }
#pragma unroll
            for (int ns = 0; ns < 4; ns++) {
                const int n0 = wn * 32 + ns * 8;
                float r0 = Bs[(kk + tig)     * BSTRIDE + n0 + gid];
                float r1 = Bs[(kk + tig + 4) * BSTRIDE + n0 + gid];
                uint32_t bh[2], bl[2];
                bh[0] = f2tf32(r0);
                bh[1] = f2tf32(r1);
                bl[0] = f2tf32(r0 - __uint_as_float(bh[0]));
                bl[1] = f2tf32(r1 - __uint_as_float(bh[1]));
#pragma unroll
                for (int ms = 0; ms < 2; ms++) {
                    mma_tf32(acc[ms][ns], af[ms], bh);
                    mma_tf32(acc[ms][ns], af[ms], bl);
                }
            }
        }
        __syncthreads();
    }

    // ---- store C ----
#pragma unroll
    for (int ms = 0; ms < 2; ms++) {
#pragma unroll
        for (int ns = 0; ns < 4; ns++) {
            int row = brow + wm * 32 + ms * 16 + gid;
            int col = bcol + wn * 32 + ns * 8 + tig * 2;
            if (col + 1 < N) {
                if (row < M) {
                    float2 v = make_float2(acc[ms][ns][0], acc[ms][ns][1]);
                    *reinterpret_cast<float2*>(&C[(size_t)row * N + col]) = v;
                }
                if (row + 8 < M) {
                    float2 v = make_float2(acc[ms][ns][2], acc[ms][ns][3]);
                    *reinterpret_cast<float2*>(&C[(size_t)(row + 8) * N + col]) = v;
                }
            }
        }
    }
}

// ---------------- GCN aggregation: agg[dst] += xw[src]*norm -----------------
// one red.global.add.v4.f32 per 16B chunk (4x fewer atomic ops than scalar)
__global__ void k_gcn_agg(const float* __restrict__ xw,
                          float* __restrict__ agg, int F) {
    const int f4  = F >> 2;
    const int tot = ET * f4;
    int gid = blockIdx.x * blockDim.x + threadIdx.x;
    if (gid >= tot) return;
    int e = gid / f4;
    int f = (gid - e * f4) << 2;
    int s = g_src[e], d = g_dst[e];
    float nrm = g_enorm[e];
    float4 v = *reinterpret_cast<const float4*>(&xw[(size_t)s * F + f]);
    red_add_v4(&agg[(size_t)d * F + f], v.x * nrm, v.y * nrm, v.z * nrm, v.w * nrm);
}

// ---------------- LayerNorm + ReLU (warp per row) ---------------------------
__global__ void k_ln_relu(const float* __restrict__ in, const float* __restrict__ g,
                          const float* __restrict__ b, float* __restrict__ out, int F) {
    int warp = (blockIdx.x * blockDim.x + threadIdx.x) >> 5;
    int lane = threadIdx.x & 31;
    if (warp >= NN) return;
    const float* row = in + (size_t)warp * F;
    float s = 0.f, s2 = 0.f;
    for (int f = lane; f < F; f += 32) {
        float v = row[f];
        s += v; s2 += v * v;
    }
#pragma unroll
    for (int o = 16; o; o >>= 1) {
        s  += __shfl_xor_sync(0xffffffffu, s,  o);
        s2 += __shfl_xor_sync(0xffffffffu, s2, o);
    }
    float mu  = s / F;
    float var = s2 / F - mu * mu;
    float inv = rsqrtf(var + LN_EPS);
    float* orow = out + (size_t)warp * F;
    for (int f = lane; f < F; f += 32) {
        float v = (row[f] - mu) * inv * g[f] + b[f];
        orow[f] = fmaxf(v, 0.f);
    }
}

// ---------------- GAT: xw = h@Wg, per-node att dots (warp per row) ----------
__global__ void k_gat_xw(const float* __restrict__ h, const float* __restrict__ Wg,
                         const float* __restrict__ asrc, const float* __restrict__ adst) {
    int row = (blockIdx.x * blockDim.x + threadIdx.x) >> 5;
    int c   = threadIdx.x & 31;
    if (row >= NN) return;
    float hv = h[(size_t)row * H3D + c];
    float o = 0.f;
#pragma unroll
    for (int k = 0; k < H3D; k++)
        o = fmaf(__shfl_sync(0xffffffffu, hv, k), Wg[k * H3D + c], o);
    g_xwg[(size_t)row * H3D + c] = o;
    float sa = o * asrc[c];
    float sd = o * adst[c];
#pragma unroll
    for (int off = 16; off; off >>= 1) {
        sa += __shfl_xor_sync(0xffffffffu, sa, off);
        sd += __shfl_xor_sync(0xffffffffu, sd, off);
    }
    if (c == 0) { g_as[row] = sa; g_ad[row] = sd; }
}

__device__ __forceinline__ float lrelu02(float a) {
    return a > 0.f ? a : 0.2f * a;
}

__device__ void atomicMaxFloat(float* addr, float value) {
    int* a = (int*)addr;
    int old = *a;
    while (__int_as_float(old) < value) {
        int assumed = old;
        old = atomicCAS(a, assumed, __float_as_int(value));
        if (old == assumed) break;
    }
}

__global__ void k_gat_amax() {
    int e = blockIdx.x * blockDim.x + threadIdx.x;
    if (e >= ET) return;
    int s = g_src[e], d = g_dst[e];
    float a = lrelu02(g_as[s] + g_ad[d]);
    atomicMaxFloat(&g_amax[d], a);
}

__global__ void k_gat_exp() {
    int e = blockIdx.x * blockDim.x + threadIdx.x;
    if (e >= ET) return;
    int s = g_src[e], d = g_dst[e];
    float a  = lrelu02(g_as[s] + g_ad[d]);
    float ev = expf(a - g_amax[d]);
    g_earr[e] = ev;
    atomicAdd(&g_denom[d], ev);
}

__global__ void k_gat_msg() {
    const int f4 = H3D >> 2;  // 8
    int gid = blockIdx.x * blockDim.x + threadIdx.x;
    if (gid >= ET * f4) return;
    int e = gid / f4;
    int f = (gid - e * f4) << 2;
    int s = g_src[e], d = g_dst[e];
    float coef = g_earr[e] / g_denom[d];
    float4 v = *reinterpret_cast<const float4*>(&g_xwg[(size_t)s * H3D + f]);
    red_add_v4(&g_aggg[(size_t)d * H3D + f],
               v.x * coef, v.y * coef, v.z * coef, v.w * coef);
}

// ---------------- bias + ReLU + mean pool -----------------------------------
__global__ void k_pool(const float* __restrict__ bg) {
    const int NPB = 1024;
    __shared__ float sp[8][H3D];
    int f = threadIdx.x;       // 0..31
    int w = threadIdx.y;       // 0..7
    int base = blockIdx.x * NPB;
    float acc = 0.f;
    for (int nd = base + w; nd < base + NPB && nd < NN; nd += 8)
        acc += fmaxf(g_aggg[(size_t)nd * H3D + f] + bg[f], 0.f);
    sp[w][f] = acc;
    __syncthreads();
    if (w == 0) {
        float t = sp[0][f];
#pragma unroll
        for (int j = 1; j < 8; j++) t += sp[j][f];
        atomicAdd(&g_pool[f], t);
    }
}

__global__ void k_final(const float* __restrict__ fcw, const float* __restrict__ fcb,
                        float* __restrict__ out) {
    int k = threadIdx.x;  // 32 threads
    float p = g_pool[k] / (float)NN;
    float c0 = p * fcw[k * 2 + 0];
    float c1 = p * fcw[k * 2 + 1];
#pragma unroll
    for (int o = 16; o; o >>= 1) {
        c0 += __shfl_xor_sync(0xffffffffu, c0, o);
        c1 += __shfl_xor_sync(0xffffffffu, c1, o);
    }
    if (k == 0) {
        out[0] = c0 + fcb[0];
        out[1] = c1 + fcb[1];
    }
}

// ---------------- launch ----------------------------------------------------
static float* sym(const void* s) {
    void* p = nullptr;
    cudaGetSymbolAddress(&p, s);
    return (float*)p;
}

extern "C" void kernel_launch(void* const* d_in, const int* in_sizes, int n_in,
                              void* d_out, int out_size) {
    const float* x    = (const float*)d_in[0];
    const void*  ei   = d_in[1];                 // int64 or int32 (probed on device)
    const float* W1   = (const float*)d_in[2];
    const float* b1   = (const float*)d_in[3];
    const float* ln1g = (const float*)d_in[4];
    const float* ln1b = (const float*)d_in[5];
    const float* W2   = (const float*)d_in[6];
    const float* b2   = (const float*)d_in[7];
    const float* ln2g = (const float*)d_in[8];
    const float* ln2b = (const float*)d_in[9];
    const float* W3   = (const float*)d_in[10];
    const float* b3   = (const float*)d_in[11];
    const float* ln3g = (const float*)d_in[12];
    const float* ln3b = (const float*)d_in[13];
    const float* Wg   = (const float*)d_in[14];
    const float* atts = (const float*)d_in[15];
    const float* attd = (const float*)d_in[16];
    const float* bg   = (const float*)d_in[17];
    const float* fcw  = (const float*)d_in[18];
    const float* fcb  = (const float*)d_in[19];
    float* out = (float*)d_out;

    float* xw1  = sym(g_xw1);   float* agg1 = sym(g_agg1); float* h1 = sym(g_h1);
    float* xw2  = sym(g_xw2);   float* agg2 = sym(g_agg2); float* h2 = sym(g_h2);
    float* xw3  = sym(g_xw3);   float* agg3 = sym(g_agg3); float* h3 = sym(g_h3);

    cudaFuncSetAttribute(k_gemm, cudaFuncAttributeMaxDynamicSharedMemorySize,
                         GEMM_SMEM_BYTES);

    const int T = 256;
    const int MGRID = (NN + GBM - 1) / GBM;   // 157

    // init + edge prep + degree
    k_init<<<(NN * H3D + T - 1) / T, T>>>();
    k_detect<<<(EE + T - 1) / T, T>>>((const long long*)ei);
    k_convert<<<(ET + T - 1) / T, T>>>(ei);
    k_dinv<<<(NN + T - 1) / T, T>>>();
    k_enorm<<<(ET + T - 1) / T, T>>>();

    // ---- GCN layer 1 ----
    k_gemm<<<dim3(H1D / GBN, MGRID), 512, GEMM_SMEM_BYTES>>>(x, W1, xw1, NN, H1D, DIN);
    k_setbias<<<(NN * H1D + T - 1) / T, T>>>(agg1, b1, NN * H1D, H1D);
    k_gcn_agg<<<(ET * (H1D / 4) + T - 1) / T, T>>>(xw1, agg1, H1D);
    k_ln_relu<<<(NN * 32 + T - 1) / T, T>>>(agg1, ln1g, ln1b, h1, H1D);

    // ---- GCN layer 2 ----
    k_gemm<<<dim3(H2D / GBN, MGRID), 512, GEMM_SMEM_BYTES>>>(h1, W2, xw2, NN, H2D, H1D);
    k_setbias<<<(NN * H2D + T - 1) / T, T>>>(agg2, b2, NN * H2D, H2D);
    k_gcn_agg<<<(ET * (H2D / 4) + T - 1) / T, T>>>(xw2, agg2, H2D);
    k_ln_relu<<<(NN * 32 + T - 1) / T, T>>>(agg2, ln2g, ln2b, h2, H2D);

    // ---- GCN layer 3 ----
    k_gemm<<<dim3(1, MGRID), 512, GEMM_SMEM_BYTES>>>(h2, W3, xw3, NN, H3D, H2D);
    k_setbias<<<(NN * H3D + T - 1) / T, T>>>(agg3, b3, NN * H3D, H3D);
    k_gcn_agg<<<(ET * (H3D / 4) + T - 1) / T, T>>>(xw3, agg3, H3D);
    k_ln_relu<<<(NN * 32 + T - 1) / T, T>>>(agg3, ln3g, ln3b, h3, H3D);

    // ---- GAT ----
    k_gat_xw<<<(NN * 32 + T - 1) / T, T>>>(h3, Wg, atts, attd);
    k_gat_amax<<<(ET + T - 1) / T, T>>>();
    k_gat_exp<<<(ET + T - 1) / T, T>>>();
    k_gat_msg<<<(ET * (H3D / 4) + T - 1) / T, T>>>();

    // ---- pool + fc ----
    k_pool<<<(NN + 1023) / 1024, dim3(32, 8)>>>(bg);
    k_final<<<1, 32>>>(fcw, fcb, out);
}

// round 8
// speedup vs baseline: 1.9674x; 1.1703x over previous
#include <cuda_runtime.h>
#include <cstdint>

#define NN   20000
#define EE   320000
#define DIN  2048
#define H1D  512
#define H2D  128
#define H3D  32
#define LN_EPS 1e-5f
#define ET   (EE + NN)   // edges incl. self loops

// ---------------- scratch (static device globals; no allocation) -------------
__device__ __align__(16) float g_xw1[NN * H1D];
__device__ __align__(16) float g_h1[NN * H1D];
__device__ __align__(16) float g_xw2[NN * H2D];
__device__ __align__(16) float g_h2[NN * H2D];
__device__ __align__(16) float g_xw3[NN * H3D];
__device__ __align__(16) float g_h3[NN * H3D];
__device__ __align__(16) float g_xwg[NN * H3D];
__device__ __align__(16) float g_hg[NN * H3D];
__device__ int   g_degi[NN];
__device__ float g_dinv[NN];
__device__ float g_as[NN];
__device__ float g_ad[NN];
__device__ int   g_src[ET];
__device__ int   g_dst[ET];
__device__ int   g_off[NN + 1];
__device__ int   g_cur[NN];
__device__ int   g_csr_src[ET];
__device__ float g_csr_w[ET];
__device__ float g_pool[H3D];
__device__ int   g_is32;

// ---------------- init ------------------------------------------------------
__global__ void k_init() {
    int i = blockIdx.x * blockDim.x + threadIdx.x;
    if (i < NN) { g_degi[i] = 0; g_cur[i] = 0; }
    if (i < H3D) g_pool[i] = 0.f;
    if (i == 0)  g_is32 = 0;
}

// Detect whether edge_index buffer is int64 or int32 (device-side probe).
__global__ void k_detect(const long long* __restrict__ ei) {
    int e = blockIdx.x * blockDim.x + threadIdx.x;
    if (e >= EE) return;
    long long v = ei[e];
    if (v < 0 || v >= NN) atomicOr(&g_is32, 1);
}

// Materialize int32 src/dst (self loops appended) and count in-degrees.
__global__ void k_convert(const void* __restrict__ ei_raw) {
    int e = blockIdx.x * blockDim.x + threadIdx.x;
    if (e >= ET) return;
    int s, d;
    if (e < EE) {
        if (g_is32) {
            const int* p = (const int*)ei_raw;
            s = p[e]; d = p[EE + e];
        } else {
            const long long* p = (const long long*)ei_raw;
            s = (int)p[e]; d = (int)p[EE + e];
        }
    } else {
        s = d = e - EE;
    }
    g_src[e] = s;
    g_dst[e] = d;
    atomicAdd(&g_degi[d], 1);
}

// Exclusive scan of g_degi into g_off (single block, 1024 threads).
#define SCAN_T 1024
#define SCAN_C ((NN + SCAN_T - 1) / SCAN_T)   // 20
__global__ __launch_bounds__(SCAN_T)
void k_scan() {
    __shared__ int sh[SCAN_T];
    int t = threadIdx.x;
    int base = t * SCAN_C;
    int local = 0;
#pragma unroll
    for (int i = 0; i < SCAN_C; i++) {
        int n = base + i;
        if (n < NN) local += g_degi[n];
    }
    sh[t] = local;
    __syncthreads();
    // Hillis-Steele inclusive scan
    for (int d = 1; d < SCAN_T; d <<= 1) {
        int v = (t >= d) ? sh[t - d] : 0;
        __syncthreads();
        sh[t] += v;
        __syncthreads();
    }
    int run = sh[t] - local;   // exclusive prefix for this chunk
#pragma unroll
    for (int i = 0; i < SCAN_C; i++) {
        int n = base + i;
        if (n < NN) { g_off[n] = run; run += g_degi[n]; }
    }
    if (t == SCAN_T - 1) g_off[NN] = run;
}

__global__ void k_dinv() {
    int i = blockIdx.x * blockDim.x + threadIdx.x;
    if (i < NN) g_dinv[i] = rsqrtf((float)g_degi[i]);
}

// Fill CSR (by dst) with src index and prefolded GCN edge weight.
__global__ void k_fill() {
    int e = blockIdx.x * blockDim.x + threadIdx.x;
    if (e >= ET) return;
    int s = g_src[e], d = g_dst[e];
    int pos = atomicAdd(&g_cur[d], 1);
    int i = g_off[d] + pos;
    g_csr_src[i] = s;
    g_csr_w[i]   = g_dinv[s] * g_dinv[d];
}

// ============ pipelined tf32 tensor-core GEMM, B hi/lo split ================
__device__ __forceinline__ uint32_t f2tf32(float x) {
    uint32_t r;
    asm("cvt.rna.tf32.f32 %0, %1;" : "=r"(r) : "f"(x));
    return r;
}

__device__ __forceinline__ void mma_tf32(float (&d)[4], const uint32_t (&a)[4],
                                         const uint32_t (&b)[2]) {
    asm volatile(
        "mma.sync.aligned.m16n8k8.row.col.f32.tf32.tf32.f32 "
        "{%0,%1,%2,%3}, {%4,%5,%6,%7}, {%8,%9}, {%0,%1,%2,%3};\n"
        : "+f"(d[0]), "+f"(d[1]), "+f"(d[2]), "+f"(d[3])
        : "r"(a[0]), "r"(a[1]), "r"(a[2]), "r"(a[3]), "r"(b[0]), "r"(b[1]));
}

__device__ __forceinline__ void cp16(uint32_t dst, const void* src, bool pred) {
    int sz = pred ? 16 : 0;
    asm volatile("cp.async.ca.shared.global [%0], [%1], 16, %2;\n"
                 :: "r"(dst), "l"(src), "r"(sz));
}
__device__ __forceinline__ void cp_commit() {
    asm volatile("cp.async.commit_group;\n");
}
template <int NMAX>
__device__ __forceinline__ void cp_wait() {
    asm volatile("cp.async.wait_group %0;\n" :: "n"(NMAX));
}

#define GBM 128
#define GBN 128
#define GBK 32
#define ASTRIDE 36
#define BSTRIDE 136
#define A_SZ (GBM * ASTRIDE)
#define B_SZ (GBK * BSTRIDE)
#define BUF_SZ (A_SZ + B_SZ)
#define GEMM_SMEM_BYTES (2 * BUF_SZ * 4)

__global__ __launch_bounds__(512)
void k_gemm(const float* __restrict__ A, const float* __restrict__ B,
            float* __restrict__ C, int M, int N, int K) {
    extern __shared__ float smem[];
    const uint32_t sbase = (uint32_t)__cvta_generic_to_shared(smem);

    const int tid  = threadIdx.x;
    const int lane = tid & 31;
    const int warp = tid >> 5;
    const int wm   = warp >> 2;
    const int wn   = warp & 3;
    const int gid  = lane >> 2;
    const int tig  = lane & 3;

    const int brow = blockIdx.y * GBM;
    const int bcol = blockIdx.x * GBN;

    const int a_m0 = (tid + 0)   >> 3, a_c0 = (tid + 0)   & 7;
    const int a_m1 = (tid + 512) >> 3, a_c1 = (tid + 512) & 7;
    const int b_k0 = (tid + 0)   >> 5, b_c0 = (tid + 0)   & 31;
    const int b_k1 = (tid + 512) >> 5, b_c1 = (tid + 512) & 31;

    const int nt = K / GBK;

    auto issue = [&](int it) {
        const int k0  = it * GBK;
        const uint32_t abase = sbase + ((it & 1) * BUF_SZ) * 4;
        const uint32_t bbase = abase + A_SZ * 4;
        {
            int gm = brow + a_m0;
            cp16(abase + (a_m0 * ASTRIDE + a_c0 * 4) * 4,
                 A + (size_t)gm * K + k0 + a_c0 * 4, gm < M);
            gm = brow + a_m1;
            cp16(abase + (a_m1 * ASTRIDE + a_c1 * 4) * 4,
                 A + (size_t)gm * K + k0 + a_c1 * 4, gm < M);
        }
        {
            int gn = bcol + b_c0 * 4;
            cp16(bbase + (b_k0 * BSTRIDE + b_c0 * 4) * 4,
                 B + (size_t)(k0 + b_k0) * N + gn, gn < N);
            gn = bcol + b_c1 * 4;
            cp16(bbase + (b_k1 * BSTRIDE + b_c1 * 4) * 4,
                 B + (size_t)(k0 + b_k1) * N + gn, gn < N);
        }
        cp_commit();
    };

    float acc[2][4][4];
#pragma unroll
    for (int i = 0; i < 2; i++)
#pragma unroll
        for (int j = 0; j < 4; j++)
#pragma unroll
            for (int r = 0; r < 4; r++) acc[i][j][r] = 0.f;

    issue(0);

    for (int it = 0; it < nt; it++) {
        if (it + 1 < nt) { issue(it + 1); cp_wait<1>(); }
        else             { cp_wait<0>(); }
        __syncthreads();

        const float* As = smem + (it & 1) * BUF_SZ;
        const float* Bs = As + A_SZ;

#pragma unroll
        for (int ks = 0; ks < 4; ks++) {
            const int kk = ks * 8;
            uint32_t af[2][4];
#pragma unroll
            for (int ms = 0; ms < 2; ms++) {
                const int m0 = wm * 32 + ms * 16;
                af[ms][0] = f2tf32(As[(m0 + gid)     * ASTRIDE + kk + tig]);
                af[ms][1] = f2tf32(As[(m0 + gid + 8) * ASTRIDE + kk + tig]);
                af[ms][2] = f2tf32(As[(m0 + gid)     * ASTRIDE + kk + tig + 4]);
                af[ms][3] = f2tf32(As[(m0 + gid + 8) * ASTRIDE + kk + tig + 4]);
            }
#pragma unroll
            for (int ns = 0; ns < 4; ns++) {
                const int n0 = wn * 32 + ns * 8;
                float r0 = Bs[(kk + tig)     * BSTRIDE + n0 + gid];
                float r1 = Bs[(kk + tig + 4) * BSTRIDE + n0 + gid];
                uint32_t bh[2], bl[2];
                bh[0] = f2tf32(r0);
                bh[1] = f2tf32(r1);
                bl[0] = f2tf32(r0 - __uint_as_float(bh[0]));
                bl[1] = f2tf32(r1 - __uint_as_float(bh[1]));
#pragma unroll
                for (int ms = 0; ms < 2; ms++) {
                    mma_tf32(acc[ms][ns], af[ms], bh);
                    mma_tf32(acc[ms][ns], af[ms], bl);
                }
            }
        }
        __syncthreads();
    }

#pragma unroll
    for (int ms = 0; ms < 2; ms++) {
#pragma unroll
        for (int ns = 0; ns < 4; ns++) {
            int row = brow + wm * 32 + ms * 16 + gid;
            int col = bcol + wn * 32 + ns * 8 + tig * 2;
            if (col + 1 < N) {
                if (row < M) {
                    float2 v = make_float2(acc[ms][ns][0], acc[ms][ns][1]);
                    *reinterpret_cast<float2*>(&C[(size_t)row * N + col]) = v;
                }
                if (row + 8 < M) {
                    float2 v = make_float2(acc[ms][ns][2], acc[ms][ns][3]);
                    *reinterpret_cast<float2*>(&C[(size_t)(row + 8) * N + col]) = v;
                }
            }
        }
    }
}

// ======== fused CSR gather + bias + LayerNorm + ReLU (one node/block) =======
// F = VEC * 128 threads. VEC=4 (F=512) uses float4 row loads; VEC=1 (F=128).
template <int F, int VEC>
__global__ __launch_bounds__(128)
void k_gcn_fused(const float* __restrict__ xw, const float* __restrict__ bconv,
                 const float* __restrict__ lng, const float* __restrict__ lnb,
                 float* __restrict__ out) {
    const int n   = blockIdx.x;
    const int tid = threadIdx.x;
    const int beg = g_off[n], end = g_off[n + 1];

    float acc[VEC];
#pragma unroll
    for (int v = 0; v < VEC; v++) acc[v] = 0.f;

    for (int idx = beg; idx < end; idx++) {
        int   s = g_csr_src[idx];
        float w = g_csr_w[idx];
        if (VEC == 4) {
            float4 r = *reinterpret_cast<const float4*>(&xw[(size_t)s * F + tid * 4]);
            acc[0] = fmaf(r.x, w, acc[0]);
            acc[1] = fmaf(r.y, w, acc[1]);
            acc[2] = fmaf(r.z, w, acc[2]);
            acc[3] = fmaf(r.w, w, acc[3]);
        } else {
            acc[0] = fmaf(xw[(size_t)s * F + tid], w, acc[0]);
        }
    }

    float sum = 0.f, sq = 0.f;
#pragma unroll
    for (int v = 0; v < VEC; v++) {
        acc[v] += bconv[tid * VEC + v];
        sum += acc[v];
        sq  += acc[v] * acc[v];
    }
    // block reduce over 128 threads (4 warps)
#pragma unroll
    for (int o = 16; o; o >>= 1) {
        sum += __shfl_xor_sync(0xffffffffu, sum, o);
        sq  += __shfl_xor_sync(0xffffffffu, sq,  o);
    }
    __shared__ float s1[4], s2[4];
    if ((tid & 31) == 0) { s1[tid >> 5] = sum; s2[tid >> 5] = sq; }
    __syncthreads();
    sum = s1[0] + s1[1] + s1[2] + s1[3];
    sq  = s2[0] + s2[1] + s2[2] + s2[3];

    float mu  = sum / F;
    float var = sq / F - mu * mu;
    float inv = rsqrtf(var + LN_EPS);
#pragma unroll
    for (int v = 0; v < VEC; v++) {
        int f = tid * VEC + v;
        float o = (acc[v] - mu) * inv * lng[f] + lnb[f];
        out[(size_t)n * F + f] = fmaxf(o, 0.f);
    }
}

// F=32 variant: one warp per node.
__global__ void k_gcn_fused32(const float* __restrict__ xw,
                              const float* __restrict__ bconv,
                              const float* __restrict__ lng,
                              const float* __restrict__ lnb,
                              float* __restrict__ out) {
    int n    = (blockIdx.x * blockDim.x + threadIdx.x) >> 5;
    int lane = threadIdx.x & 31;
    if (n >= NN) return;
    int beg = g_off[n], end = g_off[n + 1];
    float acc = 0.f;
    for (int idx = beg; idx < end; idx++)
        acc = fmaf(xw[(size_t)g_csr_src[idx] * H3D + lane], g_csr_w[idx], acc);
    acc += bconv[lane];
    float sum = acc, sq = acc * acc;
#pragma unroll
    for (int o = 16; o; o >>= 1) {
        sum += __shfl_xor_sync(0xffffffffu, sum, o);
        sq  += __shfl_xor_sync(0xffffffffu, sq,  o);
    }
    float mu  = sum / H3D;
    float var = sq / H3D - mu * mu;
    float inv = rsqrtf(var + LN_EPS);
    float o = (acc - mu) * inv * lng[lane] + lnb[lane];
    out[(size_t)n * H3D + lane] = fmaxf(o, 0.f);
}

// ---------------- GAT: xw = h@Wg, per-node att dots (warp per row) ----------
__global__ void k_gat_xw(const float* __restrict__ h, const float* __restrict__ Wg,
                         const float* __restrict__ asrc, const float* __restrict__ adst) {
    int row = (blockIdx.x * blockDim.x + threadIdx.x) >> 5;
    int c   = threadIdx.x & 31;
    if (row >= NN) return;
    float hv = h[(size_t)row * H3D + c];
    float o = 0.f;
#pragma unroll
    for (int k = 0; k < H3D; k++)
        o = fmaf(__shfl_sync(0xffffffffu, hv, k), Wg[k * H3D + c], o);
    g_xwg[(size_t)row * H3D + c] = o;
    float sa = o * asrc[c];
    float sd = o * adst[c];
#pragma unroll
    for (int off = 16; off; off >>= 1) {
        sa += __shfl_xor_sync(0xffffffffu, sa, off);
        sd += __shfl_xor_sync(0xffffffffu, sd, off);
    }
    if (c == 0) { g_as[row] = sa; g_ad[row] = sd; }
}

__device__ __forceinline__ float lrelu02(float a) {
    return a > 0.f ? a : 0.2f * a;
}

// Fused GAT softmax-aggregate: warp per node. Writes relu(out+bg).
__global__ void k_gat_fused(const float* __restrict__ bg) {
    int n    = (blockIdx.x * blockDim.x + threadIdx.x) >> 5;
    int lane = threadIdx.x & 31;
    if (n >= NN) return;
    int beg = g_off[n], end = g_off[n + 1];
    float adn = g_ad[n];

    // 1) max over in-edges
    float m = -3.0e38f;
    for (int i = beg + lane; i < end; i += 32)
        m = fmaxf(m, lrelu02(g_as[g_csr_src[i]] + adn));
#pragma unroll
    for (int o = 16; o; o >>= 1)
        m = fmaxf(m, __shfl_xor_sync(0xffffffffu, m, o));

    // 2) denom
    float den = 0.f;
    for (int i = beg + lane; i < end; i += 32)
        den += expf(lrelu02(g_as[g_csr_src[i]] + adn) - m);
#pragma unroll
    for (int o = 16; o; o >>= 1)
        den += __shfl_xor_sync(0xffffffffu, den, o);

    // 3) weighted feature sum (lane = feature)
    float acc = 0.f;
    for (int idx = beg; idx < end; idx++) {
        int s = g_csr_src[idx];
        float e = expf(lrelu02(g_as[s] + adn) - m);
        acc = fmaf(e, g_xwg[(size_t)s * H3D + lane], acc);
    }
    acc /= den;
    g_hg[(size_t)n * H3D + lane] = fmaxf(acc + bg[lane], 0.f);
}

// ---------------- mean pool + fc --------------------------------------------
__global__ void k_pool() {
    const int NPB = 1024;
    __shared__ float sp[8][H3D];
    int f = threadIdx.x;
    int w = threadIdx.y;
    int base = blockIdx.x * NPB;
    float acc = 0.f;
    for (int nd = base + w; nd < base + NPB && nd < NN; nd += 8)
        acc += g_hg[(size_t)nd * H3D + f];
    sp[w][f] = acc;
    __syncthreads();
    if (w == 0) {
        float t = sp[0][f];
#pragma unroll
        for (int j = 1; j < 8; j++) t += sp[j][f];
        atomicAdd(&g_pool[f], t);
    }
}

__global__ void k_final(const float* __restrict__ fcw, const float* __restrict__ fcb,
                        float* __restrict__ out) {
    int k = threadIdx.x;
    float p = g_pool[k] / (float)NN;
    float c0 = p * fcw[k * 2 + 0];
    float c1 = p * fcw[k * 2 + 1];
#pragma unroll
    for (int o = 16; o; o >>= 1) {
        c0 += __shfl_xor_sync(0xffffffffu, c0, o);
        c1 += __shfl_xor_sync(0xffffffffu, c1, o);
    }
    if (k == 0) {
        out[0] = c0 + fcb[0];
        out[1] = c1 + fcb[1];
    }
}

// ---------------- launch ----------------------------------------------------
static float* sym(const void* s) {
    void* p = nullptr;
    cudaGetSymbolAddress(&p, s);
    return (float*)p;
}

extern "C" void kernel_launch(void* const* d_in, const int* in_sizes, int n_in,
                              void* d_out, int out_size) {
    const float* x    = (const float*)d_in[0];
    const void*  ei   = d_in[1];
    const float* W1   = (const float*)d_in[2];
    const float* b1   = (const float*)d_in[3];
    const float* ln1g = (const float*)d_in[4];
    const float* ln1b = (const float*)d_in[5];
    const float* W2   = (const float*)d_in[6];
    const float* b2   = (const float*)d_in[7];
    const float* ln2g = (const float*)d_in[8];
    const float* ln2b = (const float*)d_in[9];
    const float* W3   = (const float*)d_in[10];
    const float* b3   = (const float*)d_in[11];
    const float* ln3g = (const float*)d_in[12];
    const float* ln3b = (const float*)d_in[13];
    const float* Wg   = (const float*)d_in[14];
    const float* atts = (const float*)d_in[15];
    const float* attd = (const float*)d_in[16];
    const float* bg   = (const float*)d_in[17];
    const float* fcw  = (const float*)d_in[18];
    const float* fcb  = (const float*)d_in[19];
    float* out = (float*)d_out;

    float* xw1 = sym(g_xw1); float* h1 = sym(g_h1);
    float* xw2 = sym(g_xw2); float* h2 = sym(g_h2);
    float* xw3 = sym(g_xw3); float* h3 = sym(g_h3);

    cudaFuncSetAttribute(k_gemm, cudaFuncAttributeMaxDynamicSharedMemorySize,
                         GEMM_SMEM_BYTES);

    const int T = 256;
    const int MGRID = (NN + GBM - 1) / GBM;

    // edge prep: probe dtype, build CSR by dst
    k_init<<<(NN + T - 1) / T, T>>>();
    k_detect<<<(EE + T - 1) / T, T>>>((const long long*)ei);
    k_convert<<<(ET + T - 1) / T, T>>>(ei);
    k_scan<<<1, SCAN_T>>>();
    k_dinv<<<(NN + T - 1) / T, T>>>();
    k_fill<<<(ET + T - 1) / T, T>>>();

    // ---- GCN layer 1 ----
    k_gemm<<<dim3(H1D / GBN, MGRID), 512, GEMM_SMEM_BYTES>>>(x, W1, xw1, NN, H1D, DIN);
    k_gcn_fused<H1D, 4><<<NN, 128>>>(xw1, b1, ln1g, ln1b, h1);

    // ---- GCN layer 2 ----
    k_gemm<<<dim3(H2D / GBN, MGRID), 512, GEMM_SMEM_BYTES>>>(h1, W2, xw2, NN, H2D, H1D);
    k_gcn_fused<H2D, 1><<<NN, 128>>>(xw2, b2, ln2g, ln2b, h2);

    // ---- GCN layer 3 ----
    k_gemm<<<dim3(1, MGRID), 512, GEMM_SMEM_BYTES>>>(h2, W3, xw3, NN, H3D, H2D);
    k_gcn_fused32<<<(NN * 32 + T - 1) / T, T>>>(xw3, b3, ln3g, ln3b, h3);

    // ---- GAT (fused) ----
    k_gat_xw<<<(NN * 32 + T - 1) / T, T>>>(h3, Wg, atts, attd);
    k_gat_fused<<<(NN * 32 + T - 1) / T, T>>>(bg);

    // ---- pool + fc ----
    k_pool<<<(NN + 1023) / 1024, dim3(32, 8)>>>();
    k_final<<<1, 32>>>(fcw, fcb, out);
}

// round 11
// speedup vs baseline: 3.0595x; 1.5551x over previous
#include <cuda_runtime.h>
#include <cuda_bf16.h>
#include <cstdint>

#define NN   20000
#define EE   320000
#define DIN  2048
#define H1D  512
#define H2D  128
#define H3D  32
#define LN_EPS 1e-5f
#define ET   (EE + NN)   // edges incl. self loops

// ---------------- scratch (static device globals; no allocation) -------------
__device__ __align__(16) float         g_xw1[NN * H1D];
__device__ __align__(16) __nv_bfloat16 g_h1b[NN * H1D];
__device__ __align__(16) float         g_xw2[NN * H2D];
__device__ __align__(16) __nv_bfloat16 g_h2b[NN * H2D];
__device__ __align__(16) float         g_xw3[NN * H3D];
__device__ __align__(16) float         g_h3[NN * H3D];
__device__ __align__(16) float         g_xwg[NN * H3D];
__device__ __align__(16) float         g_hg[NN * H3D];
__device__ __align__(16) __nv_bfloat16 g_xb[NN * DIN];
__device__ __align__(16) __nv_bfloat16 g_w1h[DIN * H1D], g_w1l[DIN * H1D];
__device__ __align__(16) __nv_bfloat16 g_w2h[H1D * H2D], g_w2l[H1D * H2D];
__device__ __align__(16) __nv_bfloat16 g_w3h[H2D * H3D], g_w3l[H2D * H3D];
__device__ int   g_degi[NN];
__device__ float g_dinv[NN];
__device__ float g_as[NN];
__device__ float g_ad[NN];
__device__ int   g_src[ET];
__device__ int   g_dst[ET];
__device__ int   g_off[NN + 1];
__device__ int   g_cur[NN];
__device__ int   g_csr_src[ET];
__device__ float g_csr_w[ET];
__device__ float g_pool[H3D];
__device__ int   g_is32;

// ---------------- init / edge prep ------------------------------------------
__global__ void k_init() {
    int i = blockIdx.x * blockDim.x + threadIdx.x;
    if (i < NN) { g_degi[i] = 0; g_cur[i] = 0; }
    if (i < H3D) g_pool[i] = 0.f;
    if (i == 0)  g_is32 = 0;
}

__global__ void k_detect(const long long* __restrict__ ei) {
    int e = blockIdx.x * blockDim.x + threadIdx.x;
    if (e >= EE) return;
    long long v = ei[e];
    if (v < 0 || v >= NN) atomicOr(&g_is32, 1);
}

__global__ void k_convert(const void* __restrict__ ei_raw) {
    int e = blockIdx.x * blockDim.x + threadIdx.x;
    if (e >= ET) return;
    int s, d;
    if (e < EE) {
        if (g_is32) {
            const int* p = (const int*)ei_raw;
            s = p[e]; d = p[EE + e];
        } else {
            const long long* p = (const long long*)ei_raw;
            s = (int)p[e]; d = (int)p[EE + e];
        }
    } else {
        s = d = e - EE;
    }
    g_src[e] = s;
    g_dst[e] = d;
    atomicAdd(&g_degi[d], 1);
}

#define SCAN_T 1024
#define SCAN_C ((NN + SCAN_T - 1) / SCAN_T)
__global__ __launch_bounds__(SCAN_T)
void k_scan() {
    __shared__ int sh[SCAN_T];
    int t = threadIdx.x;
    int base = t * SCAN_C;
    int local = 0;
#pragma unroll
    for (int i = 0; i < SCAN_C; i++) {
        int n = base + i;
        if (n < NN) local += g_degi[n];
    }
    sh[t] = local;
    __syncthreads();
    for (int d = 1; d < SCAN_T; d <<= 1) {
        int v = (t >= d) ? sh[t - d] : 0;
        __syncthreads();
        sh[t] += v;
        __syncthreads();
    }
    int run = sh[t] - local;
#pragma unroll
    for (int i = 0; i < SCAN_C; i++) {
        int n = base + i;
        if (n < NN) { g_off[n] = run; run += g_degi[n]; }
    }
    if (t == SCAN_T - 1) g_off[NN] = run;
}

__global__ void k_dinv() {
    int i = blockIdx.x * blockDim.x + threadIdx.x;
    if (i < NN) g_dinv[i] = rsqrtf((float)g_degi[i]);
}

__global__ void k_fill() {
    int e = blockIdx.x * blockDim.x + threadIdx.x;
    if (e >= ET) return;
    int s = g_src[e], d = g_dst[e];
    int pos = atomicAdd(&g_cur[d], 1);
    int i = g_off[d] + pos;
    g_csr_src[i] = s;
    g_csr_w[i]   = g_dinv[s] * g_dinv[d];
}

// ---------------- fp32 -> bf16 conversions ----------------------------------
__global__ void k_f2b(const float* __restrict__ in, __nv_bfloat16* __restrict__ o,
                      int n4) {
    int i = blockIdx.x * blockDim.x + threadIdx.x;
    if (i >= n4) return;
    float4 v = reinterpret_cast<const float4*>(in)[i];
    __nv_bfloat162 p0 = __floats2bfloat162_rn(v.x, v.y);
    __nv_bfloat162 p1 = __floats2bfloat162_rn(v.z, v.w);
    reinterpret_cast<__nv_bfloat162*>(o)[2 * i]     = p0;
    reinterpret_cast<__nv_bfloat162*>(o)[2 * i + 1] = p1;
}

__global__ void k_wsplit(const float* __restrict__ w, __nv_bfloat16* __restrict__ hi,
                         __nv_bfloat16* __restrict__ lo, int n) {
    int i = blockIdx.x * blockDim.x + threadIdx.x;
    if (i >= n) return;
    float v = w[i];
    __nv_bfloat16 h = __float2bfloat16_rn(v);
    hi[i] = h;
    lo[i] = __float2bfloat16_rn(v - __bfloat162float(h));
}

// ============ bf16 tensor-core GEMM (hi/lo B), ldmatrix + cp.async ==========
// C(fp32) = A(bf16, MxK) @ (Bh + Bl)(bf16, KxN).
// BM=128 BN=128 BK=32, 512 threads, warp tile 32x32, m16n8k16 mma.

__device__ __forceinline__ void mma_bf16(float (&d)[4], const uint32_t (&a)[4],
                                         uint32_t b0, uint32_t b1) {
    asm volatile(
        "mma.sync.aligned.m16n8k16.row.col.f32.bf16.bf16.f32 "
        "{%0,%1,%2,%3}, {%4,%5,%6,%7}, {%8,%9}, {%0,%1,%2,%3};\n"
        : "+f"(d[0]), "+f"(d[1]), "+f"(d[2]), "+f"(d[3])
        : "r"(a[0]), "r"(a[1]), "r"(a[2]), "r"(a[3]), "r"(b0), "r"(b1));
}

__device__ __forceinline__ void ldsm_x4(uint32_t& r0, uint32_t& r1, uint32_t& r2,
                                        uint32_t& r3, uint32_t addr) {
    asm volatile("ldmatrix.sync.aligned.m8n8.x4.shared.b16 {%0,%1,%2,%3}, [%4];"
                 : "=r"(r0), "=r"(r1), "=r"(r2), "=r"(r3) : "r"(addr));
}

__device__ __forceinline__ void ldsm_x4_t(uint32_t& r0, uint32_t& r1, uint32_t& r2,
                                          uint32_t& r3, uint32_t addr) {
    asm volatile("ldmatrix.sync.aligned.m8n8.x4.trans.shared.b16 {%0,%1,%2,%3}, [%4];"
                 : "=r"(r0), "=r"(r1), "=r"(r2), "=r"(r3) : "r"(addr));
}

__device__ __forceinline__ void cp16(uint32_t dst, const void* src, bool pred) {
    int sz = pred ? 16 : 0;
    asm volatile("cp.async.ca.shared.global [%0], [%1], 16, %2;\n"
                 :: "r"(dst), "l"(src), "r"(sz));
}
__device__ __forceinline__ void cp_commit() {
    asm volatile("cp.async.commit_group;\n");
}
template <int NMAX>
__device__ __forceinline__ void cp_wait() {
    asm volatile("cp.async.wait_group %0;\n" :: "n"(NMAX));
}

#define GBM 128
#define GBN 128
#define GBK 32
#define ASTR 40           // bf16; 80B rows: ldmatrix 8-row pattern conflict-free
#define BSTR 136          // bf16; 272B rows: conflict-free
#define A_ELE (GBM * ASTR)            // 5120 bf16
#define B_ELE (GBK * BSTR)            // 4352 bf16
#define BUF_ELE (A_ELE + 2 * B_ELE)   // 13824 bf16
#define GEMM_SMEM_BYTES (2 * BUF_ELE * 2)  // 55296 B

__global__ __launch_bounds__(512)
void k_gemm(const __nv_bfloat16* __restrict__ A, const __nv_bfloat16* __restrict__ Bh,
            const __nv_bfloat16* __restrict__ Bl, float* __restrict__ C,
            int M, int N, int K) {
    extern __shared__ __nv_bfloat16 smem[];
    const uint32_t sbase = (uint32_t)__cvta_generic_to_shared(smem);

    const int tid  = threadIdx.x;
    const int lane = tid & 31;
    const int warp = tid >> 5;
    const int wm   = warp >> 2;       // 0..3
    const int wn   = warp & 3;        // 0..3
    const int gid  = lane >> 2;
    const int tig  = lane & 3;

    const int brow = blockIdx.y * GBM;
    const int bcol = blockIdx.x * GBN;

    const int a_row = tid >> 2,  a_ch = tid & 3;
    const int b_row = tid >> 4,  b_ch = tid & 15;

    const int nt = K / GBK;

    auto issue = [&](int it) {
        const int k0 = it * GBK;
        const uint32_t buf = sbase + ((it & 1) * BUF_ELE) * 2;
        {
            int gm = brow + a_row;
            cp16(buf + (a_row * ASTR + a_ch * 8) * 2,
                 A + (size_t)gm * K + k0 + a_ch * 8, gm < M);
        }
        {
            int gn = bcol + b_ch * 8;
            bool p = gn < N;
            const size_t go = (size_t)(k0 + b_row) * N + gn;
            cp16(buf + (A_ELE + b_row * BSTR + b_ch * 8) * 2, Bh + go, p);
            cp16(buf + (A_ELE + B_ELE + b_row * BSTR + b_ch * 8) * 2, Bl + go, p);
        }
        cp_commit();
    };

    float acc[2][4][4];
#pragma unroll
    for (int i = 0; i < 2; i++)
#pragma unroll
        for (int j = 0; j < 4; j++)
#pragma unroll
            for (int r = 0; r < 4; r++) acc[i][j][r] = 0.f;

    const int lrow = lane & 15;         // row within 16
    const int lcol = (lane >> 4) * 8;   // 0 or 8

    issue(0);

    for (int it = 0; it < nt; it++) {
        if (it + 1 < nt) { issue(it + 1); cp_wait<1>(); }
        else             { cp_wait<0>(); }
        __syncthreads();

        const uint32_t buf  = sbase + ((it & 1) * BUF_ELE) * 2;
        const uint32_t aS   = buf;
        const uint32_t bhS  = buf + A_ELE * 2;
        const uint32_t blS  = buf + (A_ELE + B_ELE) * 2;

#pragma unroll
        for (int ks = 0; ks < 2; ks++) {
            const int kk = ks * 16;
            uint32_t a[2][4], bh[2][4], bl[2][4];
#pragma unroll
            for (int ms = 0; ms < 2; ms++) {
                int m0 = wm * 32 + ms * 16;
                uint32_t ad = aS + ((m0 + lrow) * ASTR + kk + lcol) * 2;
                ldsm_x4(a[ms][0], a[ms][1], a[ms][2], a[ms][3], ad);
            }
#pragma unroll
            for (int np = 0; np < 2; np++) {
                int n0 = wn * 32 + np * 16;
                uint32_t bd = bhS + ((kk + lrow) * BSTR + n0 + lcol) * 2;
                ldsm_x4_t(bh[np][0], bh[np][1], bh[np][2], bh[np][3], bd);
                bd = blS + ((kk + lrow) * BSTR + n0 + lcol) * 2;
                ldsm_x4_t(bl[np][0], bl[np][1], bl[np][2], bl[np][3], bd);
            }
#pragma unroll
            for (int ms = 0; ms < 2; ms++)
#pragma unroll
                for (int ns = 0; ns < 4; ns++) {
                    int np = ns >> 1, r = (ns & 1) * 2;
                    mma_bf16(acc[ms][ns], a[ms], bh[np][r], bh[np][r + 1]);
                    mma_bf16(acc[ms][ns], a[ms], bl[np][r], bl[np][r + 1]);
                }
        }
        __syncthreads();
    }

#pragma unroll
    for (int ms = 0; ms < 2; ms++) {
#pragma unroll
        for (int ns = 0; ns < 4; ns++) {
            int row = brow + wm * 32 + ms * 16 + gid;
            int col = bcol + wn * 32 + ns * 8 + tig * 2;
            if (col + 1 < N) {
                if (row < M) {
                    float2 v = make_float2(acc[ms][ns][0], acc[ms][ns][1]);
                    *reinterpret_cast<float2*>(&C[(size_t)row * N + col]) = v;
                }
                if (row + 8 < M) {
                    float2 v = make_float2(acc[ms][ns][2], acc[ms][ns][3]);
                    *reinterpret_cast<float2*>(&C[(size_t)(row + 8) * N + col]) = v;
                }
            }
        }
    }
}

// ======== fused CSR gather + bias + LayerNorm + ReLU, bf16 output ===========
template <int F, int VEC>
__global__ __launch_bounds__(128)
void k_gcn_fused(const float* __restrict__ xw, const float* __restrict__ bconv,
                 const float* __restrict__ lng, const float* __restrict__ lnb,
                 __nv_bfloat16* __restrict__ out) {
    const int n   = blockIdx.x;
    const int tid = threadIdx.x;
    const int beg = g_off[n], end = g_off[n + 1];

    float acc[VEC];
#pragma unroll
    for (int v = 0; v < VEC; v++) acc[v] = 0.f;

    for (int idx = beg; idx < end; idx++) {
        int   s = g_csr_src[idx];
        float w = g_csr_w[idx];
        if (VEC == 4) {
            float4 r = *reinterpret_cast<const float4*>(&xw[(size_t)s * F + tid * 4]);
            acc[0] = fmaf(r.x, w, acc[0]);
            acc[1] = fmaf(r.y, w, acc[1]);
            acc[2] = fmaf(r.z, w, acc[2]);
            acc[3] = fmaf(r.w, w, acc[3]);
        } else {
            acc[0] = fmaf(xw[(size_t)s * F + tid], w, acc[0]);
        }
    }

    float sum = 0.f, sq = 0.f;
#pragma unroll
    for (int v = 0; v < VEC; v++) {
        acc[v] += bconv[tid * VEC + v];
        sum += acc[v];
        sq  += acc[v] * acc[v];
    }
#pragma unroll
    for (int o = 16; o; o >>= 1) {
        sum += __shfl_xor_sync(0xffffffffu, sum, o);
        sq  += __shfl_xor_sync(0xffffffffu, sq,  o);
    }
    __shared__ float s1[4], s2[4];
    if ((tid & 31) == 0) { s1[tid >> 5] = sum; s2[tid >> 5] = sq; }
    __syncthreads();
    sum = s1[0] + s1[1] + s1[2] + s1[3];
    sq  = s2[0] + s2[1] + s2[2] + s2[3];

    float mu  = sum / F;
    float var = sq / F - mu * mu;
    float inv = rsqrtf(var + LN_EPS);
    if (VEC == 4) {
        float o0 = fmaxf((acc[0] - mu) * inv * lng[tid * 4 + 0] + lnb[tid * 4 + 0], 0.f);
        float o1 = fmaxf((acc[1] - mu) * inv * lng[tid * 4 + 1] + lnb[tid * 4 + 1], 0.f);
        float o2 = fmaxf((acc[2] - mu) * inv * lng[tid * 4 + 2] + lnb[tid * 4 + 2], 0.f);
        float o3 = fmaxf((acc[3] - mu) * inv * lng[tid * 4 + 3] + lnb[tid * 4 + 3], 0.f);
        __nv_bfloat162 p0 = __floats2bfloat162_rn(o0, o1);
        __nv_bfloat162 p1 = __floats2bfloat162_rn(o2, o3);
        __nv_bfloat162* dst = reinterpret_cast<__nv_bfloat162*>(&out[(size_t)n * F + tid * 4]);
        dst[0] = p0; dst[1] = p1;
    } else {
        float o = (acc[0] - mu) * inv * lng[tid] + lnb[tid];
        out[(size_t)n * F + tid] = __float2bfloat16_rn(fmaxf(o, 0.f));
    }
}

// F=32 variant: one warp per node, fp32 out (feeds GAT).
__global__ void k_gcn_fused32(const float* __restrict__ xw,
                              const float* __restrict__ bconv,
                              const float* __restrict__ lng,
                              const float* __restrict__ lnb,
                              float* __restrict__ out) {
    int n    = (blockIdx.x * blockDim.x + threadIdx.x) >> 5;
    int lane = threadIdx.x & 31;
    if (n >= NN) return;
    int beg = g_off[n], end = g_off[n + 1];
    float acc = 0.f;
    for (int idx = beg; idx < end; idx++)
        acc = fmaf(xw[(size_t)g_csr_src[idx] * H3D + lane], g_csr_w[idx], acc);
    acc += bconv[lane];
    float sum = acc, sq = acc * acc;
#pragma unroll
    for (int o = 16; o; o >>= 1) {
        sum += __shfl_xor_sync(0xffffffffu, sum, o);
        sq  += __shfl_xor_sync(0xffffffffu, sq,  o);
    }
    float mu  = sum / H3D;
    float var = sq / H3D - mu * mu;
    float inv = rsqrtf(var + LN_EPS);
    float o = (acc - mu) * inv * lng[lane] + lnb[lane];
    out[(size_t)n * H3D + lane] = fmaxf(o, 0.f);
}

// ---------------- GAT -------------------------------------------------------
__global__ void k_gat_xw(const float* __restrict__ h, const float* __restrict__ Wg,
                         const float* __restrict__ asrc, const float* __restrict__ adst) {
    int row = (blockIdx.x * blockDim.x + threadIdx.x) >> 5;
    int c   = threadIdx.x & 31;
    if (row >= NN) return;
    float hv = h[(size_t)row * H3D + c];
    float o = 0.f;
#pragma unroll
    for (int k = 0; k < H3D; k++)
        o = fmaf(__shfl_sync(0xffffffffu, hv, k), Wg[k * H3D + c], o);
    g_xwg[(size_t)row * H3D + c] = o;
    float sa = o * asrc[c];
    float sd = o * adst[c];
#pragma unroll
    for (int off = 16; off; off >>= 1) {
        sa += __shfl_xor_sync(0xffffffffu, sa, off);
        sd += __shfl_xor_sync(0xffffffffu, sd, off);
    }
    if (c == 0) { g_as[row] = sa; g_ad[row] = sd; }
}

__device__ __forceinline__ float lrelu02(float a) {
    return a > 0.f ? a : 0.2f * a;
}

__global__ void k_gat_fused(const float* __restrict__ bg) {
    int n    = (blockIdx.x * blockDim.x + threadIdx.x) >> 5;
    int lane = threadIdx.x & 31;
    if (n >= NN) return;
    int beg = g_off[n], end = g_off[n + 1];
    float adn = g_ad[n];

    float m = -3.0e38f;
    for (int i = beg + lane; i < end; i += 32)
        m = fmaxf(m, lrelu02(g_as[g_csr_src[i]] + adn));
#pragma unroll
    for (int o = 16; o; o >>= 1)
        m = fmaxf(m, __shfl_xor_sync(0xffffffffu, m, o));

    float den = 0.f;
    for (int i = beg + lane; i < end; i += 32)
        den += expf(lrelu02(g_as[g_csr_src[i]] + adn) - m);
#pragma unroll
    for (int o = 16; o; o >>= 1)
        den += __shfl_xor_sync(0xffffffffu, den, o);

    float acc = 0.f;
    for (int idx = beg; idx < end; idx++) {
        int s = g_csr_src[idx];
        float e = expf(lrelu02(g_as[s] + adn) - m);
        acc = fmaf(e, g_xwg[(size_t)s * H3D + lane], acc);
    }
    acc /= den;
    g_hg[(size_t)n * H3D + lane] = fmaxf(acc + bg[lane], 0.f);
}

// ---------------- mean pool + fc --------------------------------------------
__global__ void k_pool() {
    const int NPB = 1024;
    __shared__ float sp[8][H3D];
    int f = threadIdx.x;
    int w = threadIdx.y;
    int base = blockIdx.x * NPB;
    float acc = 0.f;
    for (int nd = base + w; nd < base + NPB && nd < NN; nd += 8)
        acc += g_hg[(size_t)nd * H3D + f];
    sp[w][f] = acc;
    __syncthreads();
    if (w == 0) {
        float t = sp[0][f];
#pragma unroll
        for (int j = 1; j < 8; j++) t += sp[j][f];
        atomicAdd(&g_pool[f], t);
    }
}

__global__ void k_final(const float* __restrict__ fcw, const float* __restrict__ fcb,
                        float* __restrict__ out) {
    int k = threadIdx.x;
    float p = g_pool[k] / (float)NN;
    float c0 = p * fcw[k * 2 + 0];
    float c1 = p * fcw[k * 2 + 1];
#pragma unroll
    for (int o = 16; o; o >>= 1) {
        c0 += __shfl_xor_sync(0xffffffffu, c0, o);
        c1 += __shfl_xor_sync(0xffffffffu, c1, o);
    }
    if (k == 0) {
        out[0] = c0 + fcb[0];
        out[1] = c1 + fcb[1];
    }
}

// ---------------- launch ----------------------------------------------------
template <typename T>
static T* sym(const void* s) {
    void* p = nullptr;
    cudaGetSymbolAddress(&p, s);
    return (T*)p;
}

extern "C" void kernel_launch(void* const* d_in, const int* in_sizes, int n_in,
                              void* d_out, int out_size) {
    const float* x    = (const float*)d_in[0];
    const void*  ei   = d_in[1];
    const float* W1   = (const float*)d_in[2];
    const float* b1   = (const float*)d_in[3];
    const float* ln1g = (const float*)d_in[4];
    const float* ln1b = (const float*)d_in[5];
    const float* W2   = (const float*)d_in[6];
    const float* b2   = (const float*)d_in[7];
    const float* ln2g = (const float*)d_in[8];
    const float* ln2b = (const float*)d_in[9];
    const float* W3   = (const float*)d_in[10];
    const float* b3   = (const float*)d_in[11];
    const float* ln3g = (const float*)d_in[12];
    const float* ln3b = (const float*)d_in[13];
    const float* Wg   = (const float*)d_in[14];
    const float* atts = (const float*)d_in[15];
    const float* attd = (const float*)d_in[16];
    const float* bg   = (const float*)d_in[17];
    const float* fcw  = (const float*)d_in[18];
    const float* fcb  = (const float*)d_in[19];
    float* out = (float*)d_out;

    float* xw1 = sym<float>(g_xw1);
    float* xw2 = sym<float>(g_xw2);
    float* xw3 = sym<float>(g_xw3);
    float* h3  = sym<float>(g_h3);
    __nv_bfloat16* h1b = sym<__nv_bfloat16>(g_h1b);
    __nv_bfloat16* h2b = sym<__nv_bfloat16>(g_h2b);
    __nv_bfloat16* xb  = sym<__nv_bfloat16>(g_xb);
    __nv_bfloat16* w1h = sym<__nv_bfloat16>(g_w1h);
    __nv_bfloat16* w1l = sym<__nv_bfloat16>(g_w1l);
    __nv_bfloat16* w2h = sym<__nv_bfloat16>(g_w2h);
    __nv_bfloat16* w2l = sym<__nv_bfloat16>(g_w2l);
    __nv_bfloat16* w3h = sym<__nv_bfloat16>(g_w3h);
    __nv_bfloat16* w3l = sym<__nv_bfloat16>(g_w3l);

    cudaFuncSetAttribute(k_gemm, cudaFuncAttributeMaxDynamicSharedMemorySize,
                         GEMM_SMEM_BYTES);

    const int T = 256;
    const int MGRID = (NN + GBM - 1) / GBM;

    // edge prep + operand conversion
    k_init<<<(NN + T - 1) / T, T>>>();
    k_detect<<<(EE + T - 1) / T, T>>>((const long long*)ei);
    k_convert<<<(ET + T - 1) / T, T>>>(ei);
    k_scan<<<1, SCAN_T>>>();
    k_dinv<<<(NN + T - 1) / T, T>>>();
    k_fill<<<(ET + T - 1) / T, T>>>();
    k_f2b<<<(NN * DIN / 4 + T - 1) / T, T>>>(x, xb, NN * DIN / 4);
    k_wsplit<<<(DIN * H1D + T - 1) / T, T>>>(W1, w1h, w1l, DIN * H1D);
    k_wsplit<<<(H1D * H2D + T - 1) / T, T>>>(W2, w2h, w2l, H1D * H2D);
    k_wsplit<<<(H2D * H3D + T - 1) / T, T>>>(W3, w3h, w3l, H2D * H3D);

    // ---- GCN layer 1 ----
    k_gemm<<<dim3(H1D / GBN, MGRID), 512, GEMM_SMEM_BYTES>>>(xb, w1h, w1l, xw1,
                                                             NN, H1D, DIN);
    k_gcn_fused<H1D, 4><<<NN, 128>>>(xw1, b1, ln1g, ln1b, h1b);

    // ---- GCN layer 2 ----
    k_gemm<<<dim3(1, MGRID), 512, GEMM_SMEM_BYTES>>>(h1b, w2h, w2l, xw2,
                                                     NN, H2D, H1D);
    k_gcn_fused<H2D, 1><<<NN, 128>>>(xw2, b2, ln2g, ln2b, h2b);

    // ---- GCN layer 3 ----
    k_gemm<<<dim3(1, MGRID), 512, GEMM_SMEM_BYTES>>>(h2b, w3h, w3l, xw3,
                                                     NN, H3D, H2D);
    k_gcn_fused32<<<(NN * 32 + T - 1) / T, T>>>(xw3, b3, ln3g, ln3b, h3);

    // ---- GAT (fused) ----
    k_gat_xw<<<(NN * 32 + T - 1) / T, T>>>(h3, Wg, atts, attd);
    k_gat_fused<<<(NN * 32 + T - 1) / T, T>>>(bg);

    // ---- pool + fc ----
    k_pool<<<(NN + 1023) / 1024, dim3(32, 8)>>>();
    k_final<<<1, 32>>>(fcw, fcb, out);
}

// round 13
// speedup vs baseline: 3.1128x; 1.0174x over previous
#include <cuda_runtime.h>
#include <cuda_bf16.h>
#include <cstdint>

#define NN   20000
#define EE   320000
#define DIN  2048
#define H1D  512
#define H2D  128
#define H3D  32
#define LN_EPS 1e-5f
#define ET   (EE + NN)   // edges incl. self loops

// ---------------- scratch (static device globals; no allocation) -------------
__device__ __align__(16) __nv_bfloat16 g_xw1b[NN * H1D];
__device__ __align__(16) __nv_bfloat16 g_h1b[NN * H1D];
__device__ __align__(16) __nv_bfloat16 g_xw2b[NN * H2D];
__device__ __align__(16) __nv_bfloat16 g_h2b[NN * H2D];
__device__ __align__(16) float         g_xw3[NN * H3D];
__device__ __align__(16) float         g_h3[NN * H3D];
__device__ __align__(16) float         g_xwg[NN * H3D];
__device__ __align__(16) float         g_hg[NN * H3D];
__device__ __align__(16) __nv_bfloat16 g_xb[NN * DIN];
__device__ __align__(16) __nv_bfloat16 g_w1h[DIN * H1D], g_w1l[DIN * H1D];
__device__ __align__(16) __nv_bfloat16 g_w2h[H1D * H2D], g_w2l[H1D * H2D];
__device__ __align__(16) __nv_bfloat16 g_w3h[H2D * H3D], g_w3l[H2D * H3D];
__device__ int   g_degi[NN];
__device__ float g_dinv[NN];
__device__ float g_as[NN];
__device__ float g_ad[NN];
__device__ int   g_src[ET];
__device__ int   g_dst[ET];
__device__ int   g_off[NN + 1];
__device__ int   g_cur[NN];
__device__ int   g_csr_src[ET];
__device__ float g_csr_w[ET];
__device__ float g_pool[H3D];
__device__ int   g_is32;

// ---------------- init / edge prep ------------------------------------------
__global__ void k_init() {
    int i = blockIdx.x * blockDim.x + threadIdx.x;
    if (i < NN) { g_degi[i] = 0; g_cur[i] = 0; }
    if (i < H3D) g_pool[i] = 0.f;
    if (i == 0)  g_is32 = 0;
}

__global__ void k_detect(const long long* __restrict__ ei) {
    int e = blockIdx.x * blockDim.x + threadIdx.x;
    if (e >= EE) return;
    long long v = ei[e];
    if (v < 0 || v >= NN) atomicOr(&g_is32, 1);
}

__global__ void k_convert(const void* __restrict__ ei_raw) {
    int e = blockIdx.x * blockDim.x + threadIdx.x;
    if (e >= ET) return;
    int s, d;
    if (e < EE) {
        if (g_is32) {
            const int* p = (const int*)ei_raw;
            s = p[e]; d = p[EE + e];
        } else {
            const long long* p = (const long long*)ei_raw;
            s = (int)p[e]; d = (int)p[EE + e];
        }
    } else {
        s = d = e - EE;
    }
    g_src[e] = s;
    g_dst[e] = d;
    atomicAdd(&g_degi[d], 1);
}

#define SCAN_T 1024
#define SCAN_C ((NN + SCAN_T - 1) / SCAN_T)
__global__ __launch_bounds__(SCAN_T)
void k_scan() {
    __shared__ int sh[SCAN_T];
    int t = threadIdx.x;
    int base = t * SCAN_C;
    int local = 0;
#pragma unroll
    for (int i = 0; i < SCAN_C; i++) {
        int n = base + i;
        if (n < NN) local += g_degi[n];
    }
    sh[t] = local;
    __syncthreads();
    for (int d = 1; d < SCAN_T; d <<= 1) {
        int v = (t >= d) ? sh[t - d] : 0;
        __syncthreads();
        sh[t] += v;
        __syncthreads();
    }
    int run = sh[t] - local;
#pragma unroll
    for (int i = 0; i < SCAN_C; i++) {
        int n = base + i;
        if (n < NN) { g_off[n] = run; run += g_degi[n]; }
    }
    if (t == SCAN_T - 1) g_off[NN] = run;
}

__global__ void k_dinv() {
    int i = blockIdx.x * blockDim.x + threadIdx.x;
    if (i < NN) g_dinv[i] = rsqrtf((float)g_degi[i]);
}

__global__ void k_fill() {
    int e = blockIdx.x * blockDim.x + threadIdx.x;
    if (e >= ET) return;
    int s = g_src[e], d = g_dst[e];
    int pos = atomicAdd(&g_cur[d], 1);
    int i = g_off[d] + pos;
    g_csr_src[i] = s;
    g_csr_w[i]   = g_dinv[s] * g_dinv[d];
}

// ---------------- fp32 -> bf16 conversions ----------------------------------
__global__ void k_f2b(const float* __restrict__ in, __nv_bfloat16* __restrict__ o,
                      int n4) {
    int i = blockIdx.x * blockDim.x + threadIdx.x;
    if (i >= n4) return;
    float4 v = reinterpret_cast<const float4*>(in)[i];
    __nv_bfloat162 p0 = __floats2bfloat162_rn(v.x, v.y);
    __nv_bfloat162 p1 = __floats2bfloat162_rn(v.z, v.w);
    reinterpret_cast<__nv_bfloat162*>(o)[2 * i]     = p0;
    reinterpret_cast<__nv_bfloat162*>(o)[2 * i + 1] = p1;
}

__global__ void k_wsplit(const float* __restrict__ w, __nv_bfloat16* __restrict__ hi,
                         __nv_bfloat16* __restrict__ lo, int n) {
    int i = blockIdx.x * blockDim.x + threadIdx.x;
    if (i >= n) return;
    float v = w[i];
    __nv_bfloat16 h = __float2bfloat16_rn(v);
    hi[i] = h;
    lo[i] = __float2bfloat16_rn(v - __bfloat162float(h));
}

// ============ bf16 tensor-core GEMM (hi/lo B), ldmatrix + cp.async ==========
// C = A(bf16, MxK) @ (Bh + Bl)(bf16, KxN), fp32 accum; OutT = float or bf16.
// BM=128 BN=128 BK=32, 512 threads, warp tile 32x32, m16n8k16 mma.

__device__ __forceinline__ void mma_bf16(float (&d)[4], const uint32_t (&a)[4],
                                         uint32_t b0, uint32_t b1) {
    asm volatile(
        "mma.sync.aligned.m16n8k16.row.col.f32.bf16.bf16.f32 "
        "{%0,%1,%2,%3}, {%4,%5,%6,%7}, {%8,%9}, {%0,%1,%2,%3};\n"
        : "+f"(d[0]), "+f"(d[1]), "+f"(d[2]), "+f"(d[3])
        : "r"(a[0]), "r"(a[1]), "r"(a[2]), "r"(a[3]), "r"(b0), "r"(b1));
}

__device__ __forceinline__ void ldsm_x4(uint32_t& r0, uint32_t& r1, uint32_t& r2,
                                        uint32_t& r3, uint32_t addr) {
    asm volatile("ldmatrix.sync.aligned.m8n8.x4.shared.b16 {%0,%1,%2,%3}, [%4];"
                 : "=r"(r0), "=r"(r1), "=r"(r2), "=r"(r3) : "r"(addr));
}

__device__ __forceinline__ void ldsm_x4_t(uint32_t& r0, uint32_t& r1, uint32_t& r2,
                                          uint32_t& r3, uint32_t addr) {
    asm volatile("ldmatrix.sync.aligned.m8n8.x4.trans.shared.b16 {%0,%1,%2,%3}, [%4];"
                 : "=r"(r0), "=r"(r1), "=r"(r2), "=r"(r3) : "r"(addr));
}

__device__ __forceinline__ void cp16(uint32_t dst, const void* src, bool pred) {
    int sz = pred ? 16 : 0;
    asm volatile("cp.async.ca.shared.global [%0], [%1], 16, %2;\n"
                 :: "r"(dst), "l"(src), "r"(sz));
}
__device__ __forceinline__ void cp_commit() {
    asm volatile("cp.async.commit_group;\n");
}
template <int NMAX>
__device__ __forceinline__ void cp_wait() {
    asm volatile("cp.async.wait_group %0;\n" :: "n"(NMAX));
}

#define GBM 128
#define GBN 128
#define GBK 32
#define ASTR 40           // bf16; 80B rows: ldmatrix 8-row pattern conflict-free
#define BSTR 136          // bf16; 272B rows: conflict-free
#define A_ELE (GBM * ASTR)
#define B_ELE (GBK * BSTR)
#define BUF_ELE (A_ELE + 2 * B_ELE)
#define GEMM_SMEM_BYTES (2 * BUF_ELE * 2)  // 55296 B

template <typename OutT>
__global__ __launch_bounds__(512)
void k_gemm(const __nv_bfloat16* __restrict__ A, const __nv_bfloat16* __restrict__ Bh,
            const __nv_bfloat16* __restrict__ Bl, OutT* __restrict__ C,
            int M, int N, int K) {
    extern __shared__ __nv_bfloat16 smem[];
    const uint32_t sbase = (uint32_t)__cvta_generic_to_shared(smem);

    const int tid  = threadIdx.x;
    const int lane = tid & 31;
    const int warp = tid >> 5;
    const int wm   = warp >> 2;
    const int wn   = warp & 3;
    const int gid  = lane >> 2;
    const int tig  = lane & 3;

    const int brow = blockIdx.y * GBM;
    const int bcol = blockIdx.x * GBN;

    const int a_row = tid >> 2,  a_ch = tid & 3;
    const int b_row = tid >> 4,  b_ch = tid & 15;

    const int nt = K / GBK;

    auto issue = [&](int it) {
        const int k0 = it * GBK;
        const uint32_t buf = sbase + ((it & 1) * BUF_ELE) * 2;
        {
            int gm = brow + a_row;
            cp16(buf + (a_row * ASTR + a_ch * 8) * 2,
                 A + (size_t)gm * K + k0 + a_ch * 8, gm < M);
        }
        {
            int gn = bcol + b_ch * 8;
            bool p = gn < N;
            const size_t go = (size_t)(k0 + b_row) * N + gn;
            cp16(buf + (A_ELE + b_row * BSTR + b_ch * 8) * 2, Bh + go, p);
            cp16(buf + (A_ELE + B_ELE + b_row * BSTR + b_ch * 8) * 2, Bl + go, p);
        }
        cp_commit();
    };

    float acc[2][4][4];
#pragma unroll
    for (int i = 0; i < 2; i++)
#pragma unroll
        for (int j = 0; j < 4; j++)
#pragma unroll
            for (int r = 0; r < 4; r++) acc[i][j][r] = 0.f;

    const int lrow = lane & 15;
    const int lcol = (lane >> 4) * 8;

    issue(0);

    for (int it = 0; it < nt; it++) {
        if (it + 1 < nt) { issue(it + 1); cp_wait<1>(); }
        else             { cp_wait<0>(); }
        __syncthreads();

        const uint32_t buf  = sbase + ((it & 1) * BUF_ELE) * 2;
        const uint32_t aS   = buf;
        const uint32_t bhS  = buf + A_ELE * 2;
        const uint32_t blS  = buf + (A_ELE + B_ELE) * 2;

#pragma unroll
        for (int ks = 0; ks < 2; ks++) {
            const int kk = ks * 16;
            uint32_t a[2][4], bh[2][4], bl[2][4];
#pragma unroll
            for (int ms = 0; ms < 2; ms++) {
                int m0 = wm * 32 + ms * 16;
                uint32_t ad = aS + ((m0 + lrow) * ASTR + kk + lcol) * 2;
                ldsm_x4(a[ms][0], a[ms][1], a[ms][2], a[ms][3], ad);
            }
#pragma unroll
            for (int np = 0; np < 2; np++) {
                int n0 = wn * 32 + np * 16;
                uint32_t bd = bhS + ((kk + lrow) * BSTR + n0 + lcol) * 2;
                ldsm_x4_t(bh[np][0], bh[np][1], bh[np][2], bh[np][3], bd);
                bd = blS + ((kk + lrow) * BSTR + n0 + lcol) * 2;
                ldsm_x4_t(bl[np][0], bl[np][1], bl[np][2], bl[np][3], bd);
            }
#pragma unroll
            for (int ms = 0; ms < 2; ms++)
#pragma unroll
                for (int ns = 0; ns < 4; ns++) {
                    int np = ns >> 1, r = (ns & 1) * 2;
                    mma_bf16(acc[ms][ns], a[ms], bh[np][r], bh[np][r + 1]);
                    mma_bf16(acc[ms][ns], a[ms], bl[np][r], bl[np][r + 1]);
                }
        }
        __syncthreads();
    }

#pragma unroll
    for (int ms = 0; ms < 2; ms++) {
#pragma unroll
        for (int ns = 0; ns < 4; ns++) {
            int row = brow + wm * 32 + ms * 16 + gid;
            int col = bcol + wn * 32 + ns * 8 + tig * 2;
            if (col + 1 < N) {
                if (row < M) {
                    if constexpr (sizeof(OutT) == 2) {
                        __nv_bfloat162 v = __floats2bfloat162_rn(acc[ms][ns][0],
                                                                 acc[ms][ns][1]);
                        *reinterpret_cast<__nv_bfloat162*>(
                            (__nv_bfloat16*)C + (size_t)row * N + col) = v;
                    } else {
                        float2 v = make_float2(acc[ms][ns][0], acc[ms][ns][1]);
                        *reinterpret_cast<float2*>((float*)C + (size_t)row * N + col) = v;
                    }
                }
                if (row + 8 < M) {
                    if constexpr (sizeof(OutT) == 2) {
                        __nv_bfloat162 v = __floats2bfloat162_rn(acc[ms][ns][2],
                                                                 acc[ms][ns][3]);
                        *reinterpret_cast<__nv_bfloat162*>(
                            (__nv_bfloat16*)C + (size_t)(row + 8) * N + col) = v;
                    } else {
                        float2 v = make_float2(acc[ms][ns][2], acc[ms][ns][3]);
                        *reinterpret_cast<float2*>((float*)C + (size_t)(row + 8) * N + col) = v;
                    }
                }
            }
        }
    }
}

// ======== fused CSR gather (bf16 in) + bias + LayerNorm + ReLU ==============
// F = VEC * 128 threads. VEC=4 (F=512): uint2 = 4 bf16 per thread per row.
// 2-edge unroll for MLP=2 across the serial edge walk.
template <int F, int VEC>
__global__ __launch_bounds__(128)
void k_gcn_fused(const __nv_bfloat16* __restrict__ xw, const float* __restrict__ bconv,
                 const float* __restrict__ lng, const float* __restrict__ lnb,
                 __nv_bfloat16* __restrict__ out) {
    const int n   = blockIdx.x;
    const int tid = threadIdx.x;
    const int beg = g_off[n], end = g_off[n + 1];

    float acc[VEC];
#pragma unroll
    for (int v = 0; v < VEC; v++) acc[v] = 0.f;

    auto addrow = [&](int s, float w) {
        if (VEC == 4) {
            uint2 r = *reinterpret_cast<const uint2*>(&xw[(size_t)s * F + tid * 4]);
            __nv_bfloat162 p0 = *reinterpret_cast<__nv_bfloat162*>(&r.x);
            __nv_bfloat162 p1 = *reinterpret_cast<__nv_bfloat162*>(&r.y);
            float2 f0 = __bfloat1622float2(p0);
            float2 f1 = __bfloat1622float2(p1);
            acc[0] = fmaf(f0.x, w, acc[0]);
            acc[1] = fmaf(f0.y, w, acc[1]);
            acc[2] = fmaf(f1.x, w, acc[2]);
            acc[3] = fmaf(f1.y, w, acc[3]);
        } else {
            acc[0] = fmaf(__bfloat162float(xw[(size_t)s * F + tid]), w, acc[0]);
        }
    };

    int idx = beg;
    for (; idx + 1 < end; idx += 2) {
        int   s0 = g_csr_src[idx],     s1 = g_csr_src[idx + 1];
        float w0 = g_csr_w[idx],       w1 = g_csr_w[idx + 1];
        addrow(s0, w0);
        addrow(s1, w1);
    }
    if (idx < end) addrow(g_csr_src[idx], g_csr_w[idx]);

    float sum = 0.f, sq = 0.f;
#pragma unroll
    for (int v = 0; v < VEC; v++) {
        acc[v] += bconv[tid * VEC + v];
        sum += acc[v];
        sq  += acc[v] * acc[v];
    }
#pragma unroll
    for (int o = 16; o; o >>= 1) {
        sum += __shfl_xor_sync(0xffffffffu, sum, o);
        sq  += __shfl_xor_sync(0xffffffffu, sq,  o);
    }
    __shared__ float s1m[4], s2m[4];
    if ((tid & 31) == 0) { s1m[tid >> 5] = sum; s2m[tid >> 5] = sq; }
    __syncthreads();
    sum = s1m[0] + s1m[1] + s1m[2] + s1m[3];
    sq  = s2m[0] + s2m[1] + s2m[2] + s2m[3];

    float mu  = sum / F;
    float var = sq / F - mu * mu;
    float inv = rsqrtf(var + LN_EPS);
    if (VEC == 4) {
        float o0 = fmaxf((acc[0] - mu) * inv * lng[tid * 4 + 0] + lnb[tid * 4 + 0], 0.f);
        float o1 = fmaxf((acc[1] - mu) * inv * lng[tid * 4 + 1] + lnb[tid * 4 + 1], 0.f);
        float o2 = fmaxf((acc[2] - mu) * inv * lng[tid * 4 + 2] + lnb[tid * 4 + 2], 0.f);
        float o3 = fmaxf((acc[3] - mu) * inv * lng[tid * 4 + 3] + lnb[tid * 4 + 3], 0.f);
        __nv_bfloat162 p0 = __floats2bfloat162_rn(o0, o1);
        __nv_bfloat162 p1 = __floats2bfloat162_rn(o2, o3);
        __nv_bfloat162* dst = reinterpret_cast<__nv_bfloat162*>(&out[(size_t)n * F + tid * 4]);
        dst[0] = p0; dst[1] = p1;
    } else {
        float o = (acc[0] - mu) * inv * lng[tid] + lnb[tid];
        out[(size_t)n * F + tid] = __float2bfloat16_rn(fmaxf(o, 0.f));
    }
}

// F=32 variant: one warp per node, fp32 in/out (feeds GAT).
__global__ void k_gcn_fused32(const float* __restrict__ xw,
                              const float* __restrict__ bconv,
                              const float* __restrict__ lng,
                              const float* __restrict__ lnb,
                              float* __restrict__ out) {
    int n    = (blockIdx.x * blockDim.x + threadIdx.x) >> 5;
    int lane = threadIdx.x & 31;
    if (n >= NN) return;
    int beg = g_off[n], end = g_off[n + 1];
    float acc = 0.f;
    int idx = beg;
    for (; idx + 1 < end; idx += 2) {
        int   s0 = g_csr_src[idx],   s1 = g_csr_src[idx + 1];
        float w0 = g_csr_w[idx],     w1 = g_csr_w[idx + 1];
        float v0 = xw[(size_t)s0 * H3D + lane];
        float v1 = xw[(size_t)s1 * H3D + lane];
        acc = fmaf(v0, w0, acc);
        acc = fmaf(v1, w1, acc);
    }
    if (idx < end)
        acc = fmaf(xw[(size_t)g_csr_src[idx] * H3D + lane], g_csr_w[idx], acc);
    acc += bconv[lane];
    float sum = acc, sq = acc * acc;
#pragma unroll
    for (int o = 16; o; o >>= 1) {
        sum += __shfl_xor_sync(0xffffffffu, sum, o);
        sq  += __shfl_xor_sync(0xffffffffu, sq,  o);
    }
    float mu  = sum / H3D;
    float var = sq / H3D - mu * mu;
    float inv = rsqrtf(var + LN_EPS);
    float o = (acc - mu) * inv * lng[lane] + lnb[lane];
    out[(size_t)n * H3D + lane] = fmaxf(o, 0.f);
}

// ---------------- GAT -------------------------------------------------------
__global__ void k_gat_xw(const float* __restrict__ h, const float* __restrict__ Wg,
                         const float* __restrict__ asrc, const float* __restrict__ adst) {
    int row = (blockIdx.x * blockDim.x + threadIdx.x) >> 5;
    int c   = threadIdx.x & 31;
    if (row >= NN) return;
    float hv = h[(size_t)row * H3D + c];
    float o = 0.f;
#pragma unroll
    for (int k = 0; k < H3D; k++)
        o = fmaf(__shfl_sync(0xffffffffu, hv, k), Wg[k * H3D + c], o);
    g_xwg[(size_t)row * H3D + c] = o;
    float sa = o * asrc[c];
    float sd = o * adst[c];
#pragma unroll
    for (int off = 16; off; off >>= 1) {
        sa += __shfl_xor_sync(0xffffffffu, sa, off);
        sd += __shfl_xor_sync(0xffffffffu, sd, off);
    }
    if (c == 0) { g_as[row] = sa; g_ad[row] = sd; }
}

__device__ __forceinline__ float lrelu02(float a) {
    return a > 0.f ? a : 0.2f * a;
}

__global__ void k_gat_fused(const float* __restrict__ bg) {
    int n    = (blockIdx.x * blockDim.x + threadIdx.x) >> 5;
    int lane = threadIdx.x & 31;
    if (n >= NN) return;
    int beg = g_off[n], end = g_off[n + 1];
    float adn = g_ad[n];

    float m = -3.0e38f;
    for (int i = beg + lane; i < end; i += 32)
        m = fmaxf(m, lrelu02(g_as[g_csr_src[i]] + adn));
#pragma unroll
    for (int o = 16; o; o >>= 1)
        m = fmaxf(m, __shfl_xor_sync(0xffffffffu, m, o));

    float den = 0.f;
    for (int i = beg + lane; i < end; i += 32)
        den += expf(lrelu02(g_as[g_csr_src[i]] + adn) - m);
#pragma unroll
    for (int o = 16; o; o >>= 1)
        den += __shfl_xor_sync(0xffffffffu, den, o);

    float acc = 0.f;
    for (int idx = beg; idx < end; idx++) {
        int s = g_csr_src[idx];
        float e = expf(lrelu02(g_as[s] + adn) - m);
        acc = fmaf(e, g_xwg[(size_t)s * H3D + lane], acc);
    }
    acc /= den;
    g_hg[(size_t)n * H3D + lane] = fmaxf(acc + bg[lane], 0.f);
}

// ---------------- mean pool + fc --------------------------------------------
__global__ void k_pool() {
    const int NPB = 1024;
    __shared__ float sp[8][H3D];
    int f = threadIdx.x;
    int w = threadIdx.y;
    int base = blockIdx.x * NPB;
    float acc = 0.f;
    for (int nd = base + w; nd < base + NPB && nd < NN; nd += 8)
        acc += g_hg[(size_t)nd * H3D + f];
    sp[w][f] = acc;
    __syncthreads();
    if (w == 0) {
        float t = sp[0][f];
#pragma unroll
        for (int j = 1; j < 8; j++) t += sp[j][f];
        atomicAdd(&g_pool[f], t);
    }
}

__global__ void k_final(const float* __restrict__ fcw, const float* __restrict__ fcb,
                        float* __restrict__ out) {
    int k = threadIdx.x;
    float p = g_pool[k] / (float)NN;
    float c0 = p * fcw[k * 2 + 0];
    float c1 = p * fcw[k * 2 + 1];
#pragma unroll
    for (int o = 16; o; o >>= 1) {
        c0 += __shfl_xor_sync(0xffffffffu, c0, o);
        c1 += __shfl_xor_sync(0xffffffffu, c1, o);
    }
    if (k == 0) {
        out[0] = c0 + fcb[0];
        out[1] = c1 + fcb[1];
    }
}

// ---------------- launch ----------------------------------------------------
template <typename T>
static T* sym(const void* s) {
    void* p = nullptr;
    cudaGetSymbolAddress(&p, s);
    return (T*)p;
}

extern "C" void kernel_launch(void* const* d_in, const int* in_sizes, int n_in,
                              void* d_out, int out_size) {
    const float* x    = (const float*)d_in[0];
    const void*  ei   = d_in[1];
    const float* W1   = (const float*)d_in[2];
    const float* b1   = (const float*)d_in[3];
    const float* ln1g = (const float*)d_in[4];
    const float* ln1b = (const float*)d_in[5];
    const float* W2   = (const float*)d_in[6];
    const float* b2   = (const float*)d_in[7];
    const float* ln2g = (const float*)d_in[8];
    const float* ln2b = (const float*)d_in[9];
    const float* W3   = (const float*)d_in[10];
    const float* b3   = (const float*)d_in[11];
    const float* ln3g = (const float*)d_in[12];
    const float* ln3b = (const float*)d_in[13];
    const float* Wg   = (const float*)d_in[14];
    const float* atts = (const float*)d_in[15];
    const float* attd = (const float*)d_in[16];
    const float* bg   = (const float*)d_in[17];
    const float* fcw  = (const float*)d_in[18];
    const float* fcb  = (const float*)d_in[19];
    float* out = (float*)d_out;

    float* xw3 = sym<float>(g_xw3);
    float* h3  = sym<float>(g_h3);
    __nv_bfloat16* xw1b = sym<__nv_bfloat16>(g_xw1b);
    __nv_bfloat16* xw2b = sym<__nv_bfloat16>(g_xw2b);
    __nv_bfloat16* h1b  = sym<__nv_bfloat16>(g_h1b);
    __nv_bfloat16* h2b  = sym<__nv_bfloat16>(g_h2b);
    __nv_bfloat16* xb   = sym<__nv_bfloat16>(g_xb);
    __nv_bfloat16* w1h  = sym<__nv_bfloat16>(g_w1h);
    __nv_bfloat16* w1l  = sym<__nv_bfloat16>(g_w1l);
    __nv_bfloat16* w2h  = sym<__nv_bfloat16>(g_w2h);
    __nv_bfloat16* w2l  = sym<__nv_bfloat16>(g_w2l);
    __nv_bfloat16* w3h  = sym<__nv_bfloat16>(g_w3h);
    __nv_bfloat16* w3l  = sym<__nv_bfloat16>(g_w3l);

    cudaFuncSetAttribute(k_gemm<__nv_bfloat16>,
                         cudaFuncAttributeMaxDynamicSharedMemorySize, GEMM_SMEM_BYTES);
    cudaFuncSetAttribute(k_gemm<float>,
                         cudaFuncAttributeMaxDynamicSharedMemorySize, GEMM_SMEM_BYTES);

    const int T = 256;
    const int MGRID = (NN + GBM - 1) / GBM;

    // edge prep + operand conversion
    k_init<<<(NN + T - 1) / T, T>>>();
    k_detect<<<(EE + T - 1) / T, T>>>((const long long*)ei);
    k_convert<<<(ET + T - 1) / T, T>>>(ei);
    k_scan<<<1, SCAN_T>>>();
    k_dinv<<<(NN + T - 1) / T, T>>>();
    k_fill<<<(ET + T - 1) / T, T>>>();
    k_f2b<<<(NN * DIN / 4 + T - 1) / T, T>>>(x, xb, NN * DIN / 4);
    k_wsplit<<<(DIN * H1D + T - 1) / T, T>>>(W1, w1h, w1l, DIN * H1D);
    k_wsplit<<<(H1D * H2D + T - 1) / T, T>>>(W2, w2h, w2l, H1D * H2D);
    k_wsplit<<<(H2D * H3D + T - 1) / T, T>>>(W3, w3h, w3l, H2D * H3D);

    // ---- GCN layer 1 ----
    k_gemm<__nv_bfloat16><<<dim3(H1D / GBN, MGRID), 512, GEMM_SMEM_BYTES>>>(
        xb, w1h, w1l, xw1b, NN, H1D, DIN);
    k_gcn_fused<H1D, 4><<<NN, 128>>>(xw1b, b1, ln1g, ln1b, h1b);

    // ---- GCN layer 2 ----
    k_gemm<__nv_bfloat16><<<dim3(1, MGRID), 512, GEMM_SMEM_BYTES>>>(
        h1b, w2h, w2l, xw2b, NN, H2D, H1D);
    k_gcn_fused<H2D, 1><<<NN, 128>>>(xw2b, b2, ln2g, ln2b, h2b);

    // ---- GCN layer 3 ----
    k_gemm<float><<<dim3(1, MGRID), 512, GEMM_SMEM_BYTES>>>(
        h2b, w3h, w3l, xw3, NN, H3D, H2D);
    k_gcn_fused32<<<(NN * 32 + T - 1) / T, T>>>(xw3, b3, ln3g, ln3b, h3);

    // ---- GAT (fused) ----
    k_gat_xw<<<(NN * 32 + T - 1) / T, T>>>(h3, Wg, atts, attd);
    k_gat_fused<<<(NN * 32 + T - 1) / T, T>>>(bg);

    // ---- pool + fc ----
    k_pool<<<(NN + 1023) / 1024, dim3(32, 8)>>>();
    k_final<<<1, 32>>>(fcw, fcb, out);
}